// round 2
// baseline (speedup 1.0000x reference)
#include <cuda_runtime.h>

#define DIMN 1024
#define NH   16
#define DH   64
#define NB   4
#define SXX  1024
#define SKK  2048   // Sx + Sy

// ---- scratch (static device allocations are allowed) ----
__device__ float g_Q[NB * NH * SXX * DH];   // 16 MB
__device__ float g_K[NB * NH * SKK * DH];   // 32 MB
__device__ float g_V[NB * NH * SKK * DH];   // 32 MB
__device__ float g_O[NB * SXX * DIMN];      // 16 MB

// ============================================================================
// GEMM: C = A @ W^T + bias.  A: [M, K] row-major, W: [N=1024, K] row-major.
// head_mode == 0: C[m*1024 + n] flat.
// head_mode == 1: C[((b*16 + n/64)*S_stride + seq_off + s)*64 + n%64],
//                 with b = m / 1024, s = m % 1024 (token rows).
// Block tile 128x128, K-tile 8, 256 threads, 8x8 per thread.
// ============================================================================
#define BM 128
#define BN 128
#define BK 8

__global__ void __launch_bounds__(256)
gemm_nt_bias(const float* __restrict__ A, const float* __restrict__ W,
             const float* __restrict__ bias, float* __restrict__ C,
             int K, int head_mode, int S_stride, int seq_off)
{
    __shared__ float As[BK][BM];
    __shared__ float Bs[BK][BN];

    const int tid = threadIdx.x;
    const int tx  = tid & 15;      // 0..15
    const int ty  = tid >> 4;      // 0..15
    const int mBase = blockIdx.y * BM;
    const int nBase = blockIdx.x * BN;

    float acc[8][8];
#pragma unroll
    for (int i = 0; i < 8; i++)
#pragma unroll
        for (int j = 0; j < 8; j++) acc[i][j] = 0.f;

    const int lr = tid >> 1;          // 0..127
    const int lc = (tid & 1) * 4;     // 0 or 4

    const float* Aptr = A + (size_t)(mBase + lr) * K + lc;
    const float* Wptr = W + (size_t)(nBase + lr) * K + lc;

    for (int k0 = 0; k0 < K; k0 += BK) {
        float4 va = *(const float4*)(Aptr + k0);
        float4 vb = *(const float4*)(Wptr + k0);
        __syncthreads();
        As[lc + 0][lr] = va.x; As[lc + 1][lr] = va.y;
        As[lc + 2][lr] = va.z; As[lc + 3][lr] = va.w;
        Bs[lc + 0][lr] = vb.x; Bs[lc + 1][lr] = vb.y;
        Bs[lc + 2][lr] = vb.z; Bs[lc + 3][lr] = vb.w;
        __syncthreads();
#pragma unroll
        for (int kk = 0; kk < BK; kk++) {
            float a[8], b[8];
#pragma unroll
            for (int i = 0; i < 4; i++) {
                a[i]     = As[kk][ty * 4 + i];
                a[4 + i] = As[kk][ty * 4 + 64 + i];
            }
#pragma unroll
            for (int j = 0; j < 4; j++) {
                b[j]     = Bs[kk][tx * 4 + j];
                b[4 + j] = Bs[kk][tx * 4 + 64 + j];
            }
#pragma unroll
            for (int i = 0; i < 8; i++)
#pragma unroll
                for (int j = 0; j < 8; j++) acc[i][j] += a[i] * b[j];
        }
    }

    // epilogue: bias + scatter
#pragma unroll
    for (int ih = 0; ih < 2; ih++) {
#pragma unroll
        for (int i = 0; i < 4; i++) {
            const int m  = mBase + ih * 64 + ty * 4 + i;
            const int bb = m >> 10;      // m / 1024
            const int s  = m & 1023;
#pragma unroll
            for (int jh = 0; jh < 2; jh++) {
                const int n0 = nBase + jh * 64 + tx * 4;
                float4 v;
                v.x = acc[ih * 4 + i][jh * 4 + 0] + bias[n0 + 0];
                v.y = acc[ih * 4 + i][jh * 4 + 1] + bias[n0 + 1];
                v.z = acc[ih * 4 + i][jh * 4 + 2] + bias[n0 + 2];
                v.w = acc[ih * 4 + i][jh * 4 + 3] + bias[n0 + 3];
                if (head_mode) {
                    const int h = n0 >> 6;
                    const int d = n0 & 63;
                    size_t idx = (((size_t)(bb * NH + h)) * S_stride + seq_off + s) * DH + d;
                    *(float4*)&C[idx] = v;
                } else {
                    *(float4*)&C[(size_t)m * DIMN + n0] = v;
                }
            }
        }
    }
}

// ============================================================================
// Flash attention: per (b, h, q-tile of 64). K/V tiles of 64, online softmax.
// smem: Qs[64][64] (pre-scaled by 1/8), KPs[64][68] (K tile, reused for P),
//       Vs[64][64].  All compute-phase LDS are float4 & near conflict-free.
// ============================================================================
#define KP_PITCH 68

__global__ void __launch_bounds__(256)
attn_kernel(const float* __restrict__ Q, const float* __restrict__ K,
            const float* __restrict__ V, float* __restrict__ O)
{
    extern __shared__ float sm[];
    float* Qs  = sm;                       // 64*64
    float* KPs = sm + 64 * 64;             // 64*68
    float* Vs  = KPs + 64 * KP_PITCH;      // 64*64

    const int tid = threadIdx.x;
    const int tx  = tid & 15;
    const int ty  = tid >> 4;
    const int qt  = blockIdx.x;   // 0..15
    const int h   = blockIdx.y;   // 0..15
    const int b   = blockIdx.z;   // 0..3

    const float* Qg = Q + (((size_t)b * NH + h) * SXX + qt * 64) * DH;
    const float* Kg = K + ((size_t)b * NH + h) * SKK * DH;
    const float* Vg = V + ((size_t)b * NH + h) * SKK * DH;

    // load Q tile, fold in 1/sqrt(Dh) = 0.125
#pragma unroll
    for (int t = tid; t < 1024; t += 256) {
        const int r = t >> 4, c = (t & 15) << 2;
        float4 v = *(const float4*)&Qg[r * 64 + c];
        v.x *= 0.125f; v.y *= 0.125f; v.z *= 0.125f; v.w *= 0.125f;
        *(float4*)&Qs[r * 64 + c] = v;
    }

    float m_i[4], l_i[4], oacc[4][4];
#pragma unroll
    for (int i = 0; i < 4; i++) {
        m_i[i] = -1e30f; l_i[i] = 0.f;
#pragma unroll
        for (int j = 0; j < 4; j++) oacc[i][j] = 0.f;
    }

    for (int kt = 0; kt < SKK / 64; kt++) {
        __syncthreads();   // prior-iter P/V consumers done (also orders Qs load)
        const float* Ktile = Kg + (size_t)kt * 64 * DH;
        const float* Vtile = Vg + (size_t)kt * 64 * DH;
#pragma unroll
        for (int t = tid; t < 1024; t += 256) {
            const int r = t >> 4, c = (t & 15) << 2;
            *(float4*)&KPs[r * KP_PITCH + c] = *(const float4*)&Ktile[r * 64 + c];
            *(float4*)&Vs[r * 64 + c]        = *(const float4*)&Vtile[r * 64 + c];
        }
        __syncthreads();

        // S = (Q/8) @ K^T  (4x4 per thread)
        float s[4][4];
#pragma unroll
        for (int i = 0; i < 4; i++)
#pragma unroll
            for (int j = 0; j < 4; j++) s[i][j] = 0.f;

#pragma unroll
        for (int d = 0; d < 64; d += 4) {
            float4 a4[4], b4[4];
#pragma unroll
            for (int i = 0; i < 4; i++)
                a4[i] = *(const float4*)&Qs[(ty * 4 + i) * 64 + d];
#pragma unroll
            for (int j = 0; j < 4; j++)
                b4[j] = *(const float4*)&KPs[(tx * 4 + j) * KP_PITCH + d];
#pragma unroll
            for (int i = 0; i < 4; i++)
#pragma unroll
                for (int j = 0; j < 4; j++)
                    s[i][j] += a4[i].x * b4[j].x + a4[i].y * b4[j].y
                             + a4[i].z * b4[j].z + a4[i].w * b4[j].w;
        }

        // online softmax: rows owned by (ty, i); reduce across the 16 tx lanes
#pragma unroll
        for (int i = 0; i < 4; i++) {
            float mx = s[i][0];
#pragma unroll
            for (int j = 1; j < 4; j++) mx = fmaxf(mx, s[i][j]);
#pragma unroll
            for (int off = 8; off; off >>= 1)
                mx = fmaxf(mx, __shfl_xor_sync(0xffffffffu, mx, off));
            const float mnew  = fmaxf(m_i[i], mx);
            const float alpha = __expf(m_i[i] - mnew);
            m_i[i] = mnew;
            float rs = 0.f;
#pragma unroll
            for (int j = 0; j < 4; j++) {
                s[i][j] = __expf(s[i][j] - mnew);
                rs += s[i][j];
            }
#pragma unroll
            for (int off = 8; off; off >>= 1)
                rs += __shfl_xor_sync(0xffffffffu, rs, off);
            l_i[i] = l_i[i] * alpha + rs;
#pragma unroll
            for (int j = 0; j < 4; j++) oacc[i][j] *= alpha;
        }

        __syncthreads();   // all K-tile reads done; reuse KPs for P
#pragma unroll
        for (int i = 0; i < 4; i++)
            *(float4*)&KPs[(ty * 4 + i) * KP_PITCH + tx * 4] =
                make_float4(s[i][0], s[i][1], s[i][2], s[i][3]);
        __syncthreads();

        // O += P @ V
#pragma unroll
        for (int k = 0; k < 64; k++) {
            const float4 v4 = *(const float4*)&Vs[k * 64 + tx * 4];
#pragma unroll
            for (int i = 0; i < 4; i++) {
                const float p = KPs[(ty * 4 + i) * KP_PITCH + k];
                oacc[i][0] += p * v4.x; oacc[i][1] += p * v4.y;
                oacc[i][2] += p * v4.z; oacc[i][3] += p * v4.w;
            }
        }
    }

    // write O back in token-major [B, Sx, DIM] layout
#pragma unroll
    for (int i = 0; i < 4; i++) {
        const float inv = 1.f / l_i[i];
        float4 v = make_float4(oacc[i][0] * inv, oacc[i][1] * inv,
                               oacc[i][2] * inv, oacc[i][3] * inv);
        const int q = qt * 64 + ty * 4 + i;
        size_t idx = ((size_t)b * SXX + q) * DIMN + h * 64 + tx * 4;
        *(float4*)&O[idx] = v;
    }
}

// ============================================================================
// launch
// ============================================================================
extern "C" void kernel_launch(void* const* d_in, const int* in_sizes, int n_in,
                              void* d_out, int out_size)
{
    const float* x     = (const float*)d_in[0];
    const float* y     = (const float*)d_in[1];
    const float* W_Kx  = (const float*)d_in[2];
    const float* b_Kx  = (const float*)d_in[3];
    const float* W_Qx  = (const float*)d_in[4];
    const float* b_Qx  = (const float*)d_in[5];
    const float* W_Vx  = (const float*)d_in[6];
    const float* b_Vx  = (const float*)d_in[7];
    const float* W_Ky  = (const float*)d_in[8];
    const float* b_Ky  = (const float*)d_in[9];
    const float* W_Vy  = (const float*)d_in[10];
    const float* b_Vy  = (const float*)d_in[11];
    const float* W_out = (const float*)d_in[12];
    const float* b_out = (const float*)d_in[13];
    float* out = (float*)d_out;

    float *Qp, *Kp, *Vp, *Op;
    cudaGetSymbolAddress((void**)&Qp, g_Q);
    cudaGetSymbolAddress((void**)&Kp, g_K);
    cudaGetSymbolAddress((void**)&Vp, g_V);
    cudaGetSymbolAddress((void**)&Op, g_O);

    const dim3 gGrid(DIMN / BN, (NB * SXX) / BM);   // (8, 32)

    // projections (epilogue scatters into head layout; Ky/Vy land at seq 1024)
    gemm_nt_bias<<<gGrid, 256>>>(x, W_Qx, b_Qx, Qp, DIMN, 1, SXX, 0);
    gemm_nt_bias<<<gGrid, 256>>>(x, W_Kx, b_Kx, Kp, DIMN, 1, SKK, 0);
    gemm_nt_bias<<<gGrid, 256>>>(y, W_Ky, b_Ky, Kp, DIMN, 1, SKK, SXX);
    gemm_nt_bias<<<gGrid, 256>>>(x, W_Vx, b_Vx, Vp, DIMN, 1, SKK, 0);
    gemm_nt_bias<<<gGrid, 256>>>(y, W_Vy, b_Vy, Vp, DIMN, 1, SKK, SXX);

    // attention
    const int ATTN_SMEM = (64 * 64 + 64 * KP_PITCH + 64 * 64) * (int)sizeof(float);
    cudaFuncSetAttribute(attn_kernel,
                         cudaFuncAttributeMaxDynamicSharedMemorySize, ATTN_SMEM);
    attn_kernel<<<dim3(16, 16, 4), 256, ATTN_SMEM>>>(Qp, Kp, Vp, Op);

    // output projection (flat token-major into d_out)
    gemm_nt_bias<<<gGrid, 256>>>(Op, W_out, b_out, out, DIMN, 0, 0, 0);
}

// round 4
// speedup vs baseline: 1.3507x; 1.3507x over previous
#include <cuda_runtime.h>
#include <cuda_bf16.h>
#include <cstdint>

#define DIMN 1024
#define NH   16
#define DH   64
#define NB   4
#define SXX  1024
#define SKK  2048   // Sx + Sy

// ---- scratch (static device allocations are allowed) ----
__device__ float g_Q[NB * NH * SXX * DH];   // 16 MB
__device__ float g_K[NB * NH * SKK * DH];   // 32 MB
__device__ float g_V[NB * NH * SKK * DH];   // 32 MB
__device__ float g_O[NB * SXX * DIMN];      // 16 MB

// bf16 hi/lo split buffers
__device__ __nv_bfloat16 g_xh[4194304], g_xl[4194304];
__device__ __nv_bfloat16 g_yh[4194304], g_yl[4194304];
__device__ __nv_bfloat16 g_Oh[4194304], g_Ol[4194304];
__device__ __nv_bfloat16 g_Wh[6 * 1048576], g_Wl[6 * 1048576];

// ============================================================================
// helpers (sm_80-era PTX only: no tcgen05/TMA — ptxas target is plain sm_103)
// ============================================================================
__device__ __forceinline__ void cp16(uint32_t s, const void* g) {
    asm volatile("cp.async.cg.shared.global [%0], [%1], 16;"
                 :: "r"(s), "l"(__cvta_generic_to_global(g)) : "memory");
}
__device__ __forceinline__ void ldsm_x4(uint32_t& r0, uint32_t& r1,
                                        uint32_t& r2, uint32_t& r3, uint32_t a) {
    asm volatile("ldmatrix.sync.aligned.m8n8.x4.shared.b16 {%0,%1,%2,%3}, [%4];"
                 : "=r"(r0), "=r"(r1), "=r"(r2), "=r"(r3) : "r"(a));
}
__device__ __forceinline__ void ldsm_x2(uint32_t& r0, uint32_t& r1, uint32_t a) {
    asm volatile("ldmatrix.sync.aligned.m8n8.x2.shared.b16 {%0,%1}, [%2];"
                 : "=r"(r0), "=r"(r1) : "r"(a));
}
__device__ __forceinline__ void mma_bf16(float* c, const uint32_t* a, const uint32_t* b) {
    asm volatile(
        "mma.sync.aligned.m16n8k16.row.col.f32.bf16.bf16.f32 "
        "{%0,%1,%2,%3}, {%4,%5,%6,%7}, {%8,%9}, {%0,%1,%2,%3};"
        : "+f"(c[0]), "+f"(c[1]), "+f"(c[2]), "+f"(c[3])
        : "r"(a[0]), "r"(a[1]), "r"(a[2]), "r"(a[3]), "r"(b[0]), "r"(b[1]));
}

// ============================================================================
// split fp32 -> bf16 hi + bf16 lo
// ============================================================================
__global__ void __launch_bounds__(256)
split_kernel(const float* __restrict__ in, __nv_bfloat16* __restrict__ hi,
             __nv_bfloat16* __restrict__ lo, int n4)
{
    int i = blockIdx.x * 256 + threadIdx.x;
    if (i >= n4) return;
    float4 v = ((const float4*)in)[i];
    __nv_bfloat16 h0 = __float2bfloat16(v.x), h1 = __float2bfloat16(v.y);
    __nv_bfloat16 h2 = __float2bfloat16(v.z), h3 = __float2bfloat16(v.w);
    __nv_bfloat16 l0 = __float2bfloat16(v.x - __bfloat162float(h0));
    __nv_bfloat16 l1 = __float2bfloat16(v.y - __bfloat162float(h1));
    __nv_bfloat16 l2 = __float2bfloat16(v.z - __bfloat162float(h2));
    __nv_bfloat16 l3 = __float2bfloat16(v.w - __bfloat162float(h3));
    ((__nv_bfloat162*)hi)[2 * i]     = __halves2bfloat162(h0, h1);
    ((__nv_bfloat162*)hi)[2 * i + 1] = __halves2bfloat162(h2, h3);
    ((__nv_bfloat162*)lo)[2 * i]     = __halves2bfloat162(l0, l1);
    ((__nv_bfloat162*)lo)[2 * i + 1] = __halves2bfloat162(l2, l3);
}

// ============================================================================
// mma.sync GEMM: C = A @ W^T + bias, bf16 hi/lo split (3 MMA passes).
// A: [4096,1024] bf16 (hi,lo); W: [1024,1024] bf16 (hi,lo), both K-major.
// Block 128x128, 8 warps (2m x 4n) of 64x32, BK=32, 2-stage cp.async.
// smem tiles: [128 rows][PITCH=40 bf16] (80B pitch -> conflict-free ldmatrix).
// ============================================================================
#define PITCH    40
#define TILE_B   (128 * PITCH * 2)           // 10240 B
#define STAGE_B  (4 * TILE_B)                // Ah, Al, Bh, Bl
#define GEMM_SMEM (2 * STAGE_B)              // 81920 B

__device__ __forceinline__ void load_stage(
    uint32_t sbase,
    const __nv_bfloat16* __restrict__ Ah, const __nv_bfloat16* __restrict__ Al,
    const __nv_bfloat16* __restrict__ Bh, const __nv_bfloat16* __restrict__ Bl,
    int mBase, int nBase, int k0, int tid)
{
    const __nv_bfloat16* srcs[4];
    srcs[0] = Ah + (size_t)mBase * 1024 + k0;
    srcs[1] = Al + (size_t)mBase * 1024 + k0;
    srcs[2] = Bh + (size_t)nBase * 1024 + k0;
    srcs[3] = Bl + (size_t)nBase * 1024 + k0;
#pragma unroll
    for (int j = 0; j < 8; ++j) {
        const int idx = j * 256 + tid;        // 0..2047
        const int t   = idx >> 9;             // tile
        const int q   = idx & 511;
        const int r   = q >> 2;               // row 0..127
        const int c   = q & 3;                // 16B chunk
        cp16(sbase + t * TILE_B + r * (PITCH * 2) + c * 16,
             srcs[t] + (size_t)r * 1024 + c * 8);
    }
}

__global__ void __launch_bounds__(256, 1)
gemm_tc(const __nv_bfloat16* __restrict__ Ah, const __nv_bfloat16* __restrict__ Al,
        const __nv_bfloat16* __restrict__ Bh, const __nv_bfloat16* __restrict__ Bl,
        const float* __restrict__ bias, float* __restrict__ C,
        int head_mode, int S_stride, int seq_off)
{
    extern __shared__ __align__(128) char smem[];
    const uint32_t sb = (uint32_t)__cvta_generic_to_shared(smem);
    const int tid = threadIdx.x;
    const int wid = tid >> 5, lid = tid & 31;
    const int mBase = blockIdx.y * 128;
    const int nBase = blockIdx.x * 128;
    const int wm = (wid >> 2) * 64;       // warp m offset in block
    const int wn = (wid & 3) * 32;        // warp n offset in block

    float acc[4][4][4];
#pragma unroll
    for (int mt = 0; mt < 4; mt++)
#pragma unroll
        for (int nt = 0; nt < 4; nt++)
#pragma unroll
            for (int e = 0; e < 4; e++) acc[mt][nt][e] = 0.f;

    // prologue: stages 0 and 1
    load_stage(sb, Ah, Al, Bh, Bl, mBase, nBase, 0, tid);
    asm volatile("cp.async.commit_group;" ::: "memory");
    load_stage(sb + STAGE_B, Ah, Al, Bh, Bl, mBase, nBase, 32, tid);
    asm volatile("cp.async.commit_group;" ::: "memory");

    // per-lane ldmatrix base offsets
    const int aRow = lid & 15, aCol = (lid >> 4) * 8;      // A x4 addressing
    const int bRow = lid & 7,  bCol = ((lid >> 3) & 1) * 8; // B x2 addressing

    for (int i = 0; i < 32; ++i) {
        if (i + 2 < 32) asm volatile("cp.async.wait_group 1;" ::: "memory");
        else            asm volatile("cp.async.wait_group 0;" ::: "memory");
        __syncthreads();

        const uint32_t st = sb + (i & 1) * STAGE_B;
        const uint32_t sAh = st, sAl = st + TILE_B;
        const uint32_t sBh = st + 2 * TILE_B, sBl = st + 3 * TILE_B;

#pragma unroll
        for (int kk = 0; kk < 32; kk += 16) {
            uint32_t ah[4][4], al[4][4], bh[4][2], bl[4][2];
#pragma unroll
            for (int mt = 0; mt < 4; mt++) {
                const uint32_t ao = (wm + mt * 16 + aRow) * (PITCH * 2) + (kk + aCol) * 2;
                ldsm_x4(ah[mt][0], ah[mt][1], ah[mt][2], ah[mt][3], sAh + ao);
                ldsm_x4(al[mt][0], al[mt][1], al[mt][2], al[mt][3], sAl + ao);
            }
#pragma unroll
            for (int nt = 0; nt < 4; nt++) {
                const uint32_t bo = (wn + nt * 8 + bRow) * (PITCH * 2) + (kk + bCol) * 2;
                ldsm_x2(bh[nt][0], bh[nt][1], sBh + bo);
                ldsm_x2(bl[nt][0], bl[nt][1], sBl + bo);
            }
#pragma unroll
            for (int mt = 0; mt < 4; mt++)
#pragma unroll
                for (int nt = 0; nt < 4; nt++) {
                    mma_bf16(acc[mt][nt], ah[mt], bh[nt]);
                    mma_bf16(acc[mt][nt], al[mt], bh[nt]);
                    mma_bf16(acc[mt][nt], ah[mt], bl[nt]);
                }
        }

        __syncthreads();   // everyone done reading this buffer
        if (i + 2 < 32) {
            load_stage(sb + (i & 1) * STAGE_B, Ah, Al, Bh, Bl,
                       mBase, nBase, (i + 2) * 32, tid);
            asm volatile("cp.async.commit_group;" ::: "memory");
        }
    }

    // epilogue: c-frag lane l: rows m0+(l>>2), m0+8+(l>>2); cols n0+(l&3)*2, +1
    const int lr = lid >> 2, lc = (lid & 3) * 2;
#pragma unroll
    for (int mt = 0; mt < 4; mt++) {
#pragma unroll
        for (int half = 0; half < 2; half++) {
            const int m = mBase + wm + mt * 16 + half * 8 + lr;
            float* outrow;
            if (head_mode) {
                const int bb = m >> 10, sdx = m & 1023;
                outrow = C + (((size_t)(bb * NH)) * S_stride + seq_off + sdx) * DH;
                // head offset added per-column below (h = n>>6)
            } else {
                outrow = C + (size_t)m * DIMN;
            }
#pragma unroll
            for (int nt = 0; nt < 4; nt++) {
                const int n = nBase + wn + nt * 8 + lc;
                float2 v;
                v.x = acc[mt][nt][half * 2 + 0] + bias[n];
                v.y = acc[mt][nt][half * 2 + 1] + bias[n + 1];
                if (head_mode) {
                    const int h = n >> 6, d = n & 63;
                    *(float2*)&outrow[(size_t)h * S_stride * DH + d] = v;
                } else {
                    *(float2*)&outrow[n] = v;
                }
            }
        }
    }
}

// ============================================================================
// Flash attention (unchanged — passing fp32 SIMT version)
// ============================================================================
#define KP_PITCH 68

__global__ void __launch_bounds__(256)
attn_kernel(const float* __restrict__ Q, const float* __restrict__ K,
            const float* __restrict__ V, float* __restrict__ O)
{
    extern __shared__ float sm[];
    float* Qs  = sm;
    float* KPs = sm + 64 * 64;
    float* Vs  = KPs + 64 * KP_PITCH;

    const int tid = threadIdx.x;
    const int tx  = tid & 15;
    const int ty  = tid >> 4;
    const int qt  = blockIdx.x;
    const int h   = blockIdx.y;
    const int b   = blockIdx.z;

    const float* Qg = Q + (((size_t)b * NH + h) * SXX + qt * 64) * DH;
    const float* Kg = K + ((size_t)b * NH + h) * SKK * DH;
    const float* Vg = V + ((size_t)b * NH + h) * SKK * DH;

#pragma unroll
    for (int t = tid; t < 1024; t += 256) {
        const int r = t >> 4, c = (t & 15) << 2;
        float4 v = *(const float4*)&Qg[r * 64 + c];
        v.x *= 0.125f; v.y *= 0.125f; v.z *= 0.125f; v.w *= 0.125f;
        *(float4*)&Qs[r * 64 + c] = v;
    }

    float m_i[4], l_i[4], oacc[4][4];
#pragma unroll
    for (int i = 0; i < 4; i++) {
        m_i[i] = -1e30f; l_i[i] = 0.f;
#pragma unroll
        for (int j = 0; j < 4; j++) oacc[i][j] = 0.f;
    }

    for (int kt = 0; kt < SKK / 64; kt++) {
        __syncthreads();
        const float* Ktile = Kg + (size_t)kt * 64 * DH;
        const float* Vtile = Vg + (size_t)kt * 64 * DH;
#pragma unroll
        for (int t = tid; t < 1024; t += 256) {
            const int r = t >> 4, c = (t & 15) << 2;
            *(float4*)&KPs[r * KP_PITCH + c] = *(const float4*)&Ktile[r * 64 + c];
            *(float4*)&Vs[r * 64 + c]        = *(const float4*)&Vtile[r * 64 + c];
        }
        __syncthreads();

        float s[4][4];
#pragma unroll
        for (int i = 0; i < 4; i++)
#pragma unroll
            for (int j = 0; j < 4; j++) s[i][j] = 0.f;

#pragma unroll
        for (int d = 0; d < 64; d += 4) {
            float4 a4[4], b4[4];
#pragma unroll
            for (int i = 0; i < 4; i++)
                a4[i] = *(const float4*)&Qs[(ty * 4 + i) * 64 + d];
#pragma unroll
            for (int j = 0; j < 4; j++)
                b4[j] = *(const float4*)&KPs[(tx * 4 + j) * KP_PITCH + d];
#pragma unroll
            for (int i = 0; i < 4; i++)
#pragma unroll
                for (int j = 0; j < 4; j++)
                    s[i][j] += a4[i].x * b4[j].x + a4[i].y * b4[j].y
                             + a4[i].z * b4[j].z + a4[i].w * b4[j].w;
        }

#pragma unroll
        for (int i = 0; i < 4; i++) {
            float mx = s[i][0];
#pragma unroll
            for (int j = 1; j < 4; j++) mx = fmaxf(mx, s[i][j]);
#pragma unroll
            for (int off = 8; off; off >>= 1)
                mx = fmaxf(mx, __shfl_xor_sync(0xffffffffu, mx, off));
            const float mnew  = fmaxf(m_i[i], mx);
            const float alpha = __expf(m_i[i] - mnew);
            m_i[i] = mnew;
            float rs = 0.f;
#pragma unroll
            for (int j = 0; j < 4; j++) {
                s[i][j] = __expf(s[i][j] - mnew);
                rs += s[i][j];
            }
#pragma unroll
            for (int off = 8; off; off >>= 1)
                rs += __shfl_xor_sync(0xffffffffu, rs, off);
            l_i[i] = l_i[i] * alpha + rs;
#pragma unroll
            for (int j = 0; j < 4; j++) oacc[i][j] *= alpha;
        }

        __syncthreads();
#pragma unroll
        for (int i = 0; i < 4; i++)
            *(float4*)&KPs[(ty * 4 + i) * KP_PITCH + tx * 4] =
                make_float4(s[i][0], s[i][1], s[i][2], s[i][3]);
        __syncthreads();

#pragma unroll
        for (int k = 0; k < 64; k++) {
            const float4 v4 = *(const float4*)&Vs[k * 64 + tx * 4];
#pragma unroll
            for (int i = 0; i < 4; i++) {
                const float p = KPs[(ty * 4 + i) * KP_PITCH + k];
                oacc[i][0] += p * v4.x; oacc[i][1] += p * v4.y;
                oacc[i][2] += p * v4.z; oacc[i][3] += p * v4.w;
            }
        }
    }

#pragma unroll
    for (int i = 0; i < 4; i++) {
        const float inv = 1.f / l_i[i];
        float4 v = make_float4(oacc[i][0] * inv, oacc[i][1] * inv,
                               oacc[i][2] * inv, oacc[i][3] * inv);
        const int q = qt * 64 + ty * 4 + i;
        size_t idx = ((size_t)b * SXX + q) * DIMN + h * 64 + tx * 4;
        *(float4*)&O[idx] = v;
    }
}

// ============================================================================
// launch
// ============================================================================
extern "C" void kernel_launch(void* const* d_in, const int* in_sizes, int n_in,
                              void* d_out, int out_size)
{
    const float* x     = (const float*)d_in[0];
    const float* y     = (const float*)d_in[1];
    const float* W_Kx  = (const float*)d_in[2];
    const float* b_Kx  = (const float*)d_in[3];
    const float* W_Qx  = (const float*)d_in[4];
    const float* b_Qx  = (const float*)d_in[5];
    const float* W_Vx  = (const float*)d_in[6];
    const float* b_Vx  = (const float*)d_in[7];
    const float* W_Ky  = (const float*)d_in[8];
    const float* b_Ky  = (const float*)d_in[9];
    const float* W_Vy  = (const float*)d_in[10];
    const float* b_Vy  = (const float*)d_in[11];
    const float* W_out = (const float*)d_in[12];
    const float* b_out = (const float*)d_in[13];
    float* out = (float*)d_out;

    float *Qp, *Kp, *Vp, *Op;
    cudaGetSymbolAddress((void**)&Qp, g_Q);
    cudaGetSymbolAddress((void**)&Kp, g_K);
    cudaGetSymbolAddress((void**)&Vp, g_V);
    cudaGetSymbolAddress((void**)&Op, g_O);
    __nv_bfloat16 *xh, *xl, *yh, *yl, *Oh, *Ol, *Wh, *Wl;
    cudaGetSymbolAddress((void**)&xh, g_xh);
    cudaGetSymbolAddress((void**)&xl, g_xl);
    cudaGetSymbolAddress((void**)&yh, g_yh);
    cudaGetSymbolAddress((void**)&yl, g_yl);
    cudaGetSymbolAddress((void**)&Oh, g_Oh);
    cudaGetSymbolAddress((void**)&Ol, g_Ol);
    cudaGetSymbolAddress((void**)&Wh, g_Wh);
    cudaGetSymbolAddress((void**)&Wl, g_Wl);

    // split inputs to bf16 hi/lo
    split_kernel<<<4096, 256>>>(x, xh, xl, 1048576);
    split_kernel<<<4096, 256>>>(y, yh, yl, 1048576);
    const float* srcW[6] = {W_Kx, W_Qx, W_Vx, W_Ky, W_Vy, W_out};
    for (int i = 0; i < 6; i++)
        split_kernel<<<1024, 256>>>(srcW[i], Wh + (size_t)i * 1048576,
                                    Wl + (size_t)i * 1048576, 262144);

    cudaFuncSetAttribute(gemm_tc, cudaFuncAttributeMaxDynamicSharedMemorySize, GEMM_SMEM);
    const dim3 gGrid(8, 32);
#define WHI(i) (Wh + (size_t)(i) * 1048576)
#define WLO(i) (Wl + (size_t)(i) * 1048576)
    gemm_tc<<<gGrid, 256, GEMM_SMEM>>>(xh, xl, WHI(1), WLO(1), b_Qx, Qp, 1, SXX, 0);
    gemm_tc<<<gGrid, 256, GEMM_SMEM>>>(xh, xl, WHI(0), WLO(0), b_Kx, Kp, 1, SKK, 0);
    gemm_tc<<<gGrid, 256, GEMM_SMEM>>>(yh, yl, WHI(3), WLO(3), b_Ky, Kp, 1, SKK, SXX);
    gemm_tc<<<gGrid, 256, GEMM_SMEM>>>(xh, xl, WHI(2), WLO(2), b_Vx, Vp, 1, SKK, 0);
    gemm_tc<<<gGrid, 256, GEMM_SMEM>>>(yh, yl, WHI(4), WLO(4), b_Vy, Vp, 1, SKK, SXX);

    // attention (SIMT fp32, unchanged)
    const int ATTN_SMEM = (64 * 64 + 64 * KP_PITCH + 64 * 64) * (int)sizeof(float);
    cudaFuncSetAttribute(attn_kernel, cudaFuncAttributeMaxDynamicSharedMemorySize, ATTN_SMEM);
    attn_kernel<<<dim3(16, 16, 4), 256, ATTN_SMEM>>>(Qp, Kp, Vp, Op);

    // output projection on tensor cores
    split_kernel<<<4096, 256>>>(Op, Oh, Ol, 1048576);
    gemm_tc<<<gGrid, 256, GEMM_SMEM>>>(Oh, Ol, WHI(5), WLO(5), b_out, out, 0, 0, 0);
}

// round 5
// speedup vs baseline: 3.0432x; 2.2531x over previous
#include <cuda_runtime.h>
#include <cuda_bf16.h>
#include <cstdint>

#define DIMN 1024
#define NH   16
#define DH   64
#define NB   4
#define SXX  1024
#define SKK  2048   // Sx + Sy

// ---- scratch (static device allocations are allowed) ----
// bf16 hi/lo pairs everywhere
__device__ __nv_bfloat16 g_xh[4194304], g_xl[4194304];
__device__ __nv_bfloat16 g_yh[4194304], g_yl[4194304];
__device__ __nv_bfloat16 g_Wh[6 * 1048576], g_Wl[6 * 1048576];
__device__ __nv_bfloat16 g_Qh[4194304],  g_Ql[4194304];   // [b,h,s,d]
__device__ __nv_bfloat16 g_Kh[8388608],  g_Kl[8388608];   // [b,h,s,d]
__device__ __nv_bfloat16 g_Vth[8388608], g_Vtl[8388608];  // [b,h,d,s] transposed
__device__ __nv_bfloat16 g_Oh[4194304],  g_Ol[4194304];   // [b,s,dim]

// ============================================================================
// helpers (sm_80-era PTX only: no tcgen05/TMA — ptxas target is plain sm_103)
// ============================================================================
__device__ __forceinline__ void cp16(uint32_t s, const void* g) {
    asm volatile("cp.async.cg.shared.global [%0], [%1], 16;"
                 :: "r"(s), "l"(__cvta_generic_to_global(g)) : "memory");
}
__device__ __forceinline__ void ldsm_x4(uint32_t& r0, uint32_t& r1,
                                        uint32_t& r2, uint32_t& r3, uint32_t a) {
    asm volatile("ldmatrix.sync.aligned.m8n8.x4.shared.b16 {%0,%1,%2,%3}, [%4];"
                 : "=r"(r0), "=r"(r1), "=r"(r2), "=r"(r3) : "r"(a));
}
__device__ __forceinline__ void ldsm_x2(uint32_t& r0, uint32_t& r1, uint32_t a) {
    asm volatile("ldmatrix.sync.aligned.m8n8.x2.shared.b16 {%0,%1}, [%2];"
                 : "=r"(r0), "=r"(r1) : "r"(a));
}
__device__ __forceinline__ void mma_bf16(float* c, const uint32_t* a, const uint32_t* b) {
    asm volatile(
        "mma.sync.aligned.m16n8k16.row.col.f32.bf16.bf16.f32 "
        "{%0,%1,%2,%3}, {%4,%5,%6,%7}, {%8,%9}, {%0,%1,%2,%3};"
        : "+f"(c[0]), "+f"(c[1]), "+f"(c[2]), "+f"(c[3])
        : "r"(a[0]), "r"(a[1]), "r"(a[2]), "r"(a[3]), "r"(b[0]), "r"(b[1]));
}
// pack two fp32 into bf16x2 register: low half = v0, high half = v1
__device__ __forceinline__ uint32_t pack_bf16(float v0, float v1) {
    uint32_t r;
    asm("cvt.rn.bf16x2.f32 %0, %1, %2;" : "=r"(r) : "f"(v1), "f"(v0));
    return r;
}

// ============================================================================
// split fp32 -> bf16 hi + bf16 lo
// ============================================================================
__global__ void __launch_bounds__(256)
split_kernel(const float* __restrict__ in, __nv_bfloat16* __restrict__ hi,
             __nv_bfloat16* __restrict__ lo, int n4)
{
    int i = blockIdx.x * 256 + threadIdx.x;
    if (i >= n4) return;
    float4 v = ((const float4*)in)[i];
    __nv_bfloat16 h0 = __float2bfloat16(v.x), h1 = __float2bfloat16(v.y);
    __nv_bfloat16 h2 = __float2bfloat16(v.z), h3 = __float2bfloat16(v.w);
    __nv_bfloat16 l0 = __float2bfloat16(v.x - __bfloat162float(h0));
    __nv_bfloat16 l1 = __float2bfloat16(v.y - __bfloat162float(h1));
    __nv_bfloat16 l2 = __float2bfloat16(v.z - __bfloat162float(h2));
    __nv_bfloat16 l3 = __float2bfloat16(v.w - __bfloat162float(h3));
    ((__nv_bfloat162*)hi)[2 * i]     = __halves2bfloat162(h0, h1);
    ((__nv_bfloat162*)hi)[2 * i + 1] = __halves2bfloat162(h2, h3);
    ((__nv_bfloat162*)lo)[2 * i]     = __halves2bfloat162(l0, l1);
    ((__nv_bfloat162*)lo)[2 * i + 1] = __halves2bfloat162(l2, l3);
}

// ============================================================================
// mma.sync GEMM: out = (A @ W^T + bias) * scale, bf16 hi/lo split (3 passes).
// mode 0: fp32 flat [m, 1024] -> outF
// mode 1: bf16 hi/lo head layout [b,h,S_stride,64] -> outH/outL
// mode 2: bf16 hi/lo TRANSPOSED head layout [b,h,64,S_stride] -> outH/outL
// ============================================================================
#define PITCH    40
#define TILE_B   (128 * PITCH * 2)           // 10240 B
#define STAGE_B  (4 * TILE_B)
#define GEMM_SMEM (2 * STAGE_B)              // 81920 B

__device__ __forceinline__ void load_stage(
    uint32_t sbase,
    const __nv_bfloat16* __restrict__ Ah, const __nv_bfloat16* __restrict__ Al,
    const __nv_bfloat16* __restrict__ Bh, const __nv_bfloat16* __restrict__ Bl,
    int mBase, int nBase, int k0, int tid)
{
    const __nv_bfloat16* srcs[4];
    srcs[0] = Ah + (size_t)mBase * 1024 + k0;
    srcs[1] = Al + (size_t)mBase * 1024 + k0;
    srcs[2] = Bh + (size_t)nBase * 1024 + k0;
    srcs[3] = Bl + (size_t)nBase * 1024 + k0;
#pragma unroll
    for (int j = 0; j < 8; ++j) {
        const int t = j >> 1;
        const int q = (j & 1) * 256 + tid;
        const int r = q >> 2;
        const int c = q & 3;
        cp16(sbase + t * TILE_B + r * (PITCH * 2) + c * 16,
             srcs[t] + (size_t)r * 1024 + c * 8);
    }
}

__global__ void __launch_bounds__(256, 1)
gemm_tc(const __nv_bfloat16* __restrict__ Ah, const __nv_bfloat16* __restrict__ Al,
        const __nv_bfloat16* __restrict__ Bh, const __nv_bfloat16* __restrict__ Bl,
        const float* __restrict__ bias, float* __restrict__ outF,
        __nv_bfloat16* __restrict__ outH, __nv_bfloat16* __restrict__ outL,
        int mode, int S_stride, int seq_off, float scale)
{
    extern __shared__ __align__(128) char smem[];
    const uint32_t sb = (uint32_t)__cvta_generic_to_shared(smem);
    const int tid = threadIdx.x;
    const int wid = tid >> 5, lid = tid & 31;
    const int mBase = blockIdx.y * 128;
    const int nBase = blockIdx.x * 128;
    const int wm = (wid >> 2) * 64;
    const int wn = (wid & 3) * 32;

    float acc[4][4][4];
#pragma unroll
    for (int mt = 0; mt < 4; mt++)
#pragma unroll
        for (int nt = 0; nt < 4; nt++)
#pragma unroll
            for (int e = 0; e < 4; e++) acc[mt][nt][e] = 0.f;

    load_stage(sb, Ah, Al, Bh, Bl, mBase, nBase, 0, tid);
    asm volatile("cp.async.commit_group;" ::: "memory");
    load_stage(sb + STAGE_B, Ah, Al, Bh, Bl, mBase, nBase, 32, tid);
    asm volatile("cp.async.commit_group;" ::: "memory");

    const int aRow = lid & 15, aCol = (lid >> 4) * 8;
    const int bRow = lid & 7,  bCol = ((lid >> 3) & 1) * 8;

    for (int i = 0; i < 32; ++i) {
        if (i + 2 < 32) asm volatile("cp.async.wait_group 1;" ::: "memory");
        else            asm volatile("cp.async.wait_group 0;" ::: "memory");
        __syncthreads();

        const uint32_t st = sb + (i & 1) * STAGE_B;
        const uint32_t sAh = st, sAl = st + TILE_B;
        const uint32_t sBh = st + 2 * TILE_B, sBl = st + 3 * TILE_B;

#pragma unroll
        for (int kk = 0; kk < 32; kk += 16) {
            uint32_t ah[4][4], al[4][4], bh[4][2], bl[4][2];
#pragma unroll
            for (int mt = 0; mt < 4; mt++) {
                const uint32_t ao = (wm + mt * 16 + aRow) * (PITCH * 2) + (kk + aCol) * 2;
                ldsm_x4(ah[mt][0], ah[mt][1], ah[mt][2], ah[mt][3], sAh + ao);
                ldsm_x4(al[mt][0], al[mt][1], al[mt][2], al[mt][3], sAl + ao);
            }
#pragma unroll
            for (int nt = 0; nt < 4; nt++) {
                const uint32_t bo = (wn + nt * 8 + bRow) * (PITCH * 2) + (kk + bCol) * 2;
                ldsm_x2(bh[nt][0], bh[nt][1], sBh + bo);
                ldsm_x2(bl[nt][0], bl[nt][1], sBl + bo);
            }
#pragma unroll
            for (int mt = 0; mt < 4; mt++)
#pragma unroll
                for (int nt = 0; nt < 4; nt++) {
                    mma_bf16(acc[mt][nt], ah[mt], bh[nt]);
                    mma_bf16(acc[mt][nt], al[mt], bh[nt]);
                    mma_bf16(acc[mt][nt], ah[mt], bl[nt]);
                }
        }

        __syncthreads();
        if (i + 2 < 32) {
            load_stage(sb + (i & 1) * STAGE_B, Ah, Al, Bh, Bl,
                       mBase, nBase, (i + 2) * 32, tid);
            asm volatile("cp.async.commit_group;" ::: "memory");
        }
    }

    const int lr = lid >> 2, lc = (lid & 3) * 2;
#pragma unroll
    for (int mt = 0; mt < 4; mt++) {
#pragma unroll
        for (int half = 0; half < 2; half++) {
            const int m  = mBase + wm + mt * 16 + half * 8 + lr;
            const int bb = m >> 10, sdx = m & 1023;
#pragma unroll
            for (int nt = 0; nt < 4; nt++) {
                const int n = nBase + wn + nt * 8 + lc;
                const float v0 = (acc[mt][nt][half * 2 + 0] + bias[n])     * scale;
                const float v1 = (acc[mt][nt][half * 2 + 1] + bias[n + 1]) * scale;
                if (mode == 0) {
                    *(float2*)&outF[(size_t)m * DIMN + n] = make_float2(v0, v1);
                } else {
                    const __nv_bfloat16 h0 = __float2bfloat16(v0);
                    const __nv_bfloat16 l0 = __float2bfloat16(v0 - __bfloat162float(h0));
                    const __nv_bfloat16 h1 = __float2bfloat16(v1);
                    const __nv_bfloat16 l1 = __float2bfloat16(v1 - __bfloat162float(h1));
                    const int hh = n >> 6, d = n & 63;
                    if (mode == 1) {
                        size_t idx = (((size_t)(bb * NH + hh)) * S_stride + seq_off + sdx) * DH + d;
                        *(__nv_bfloat162*)&outH[idx] = __halves2bfloat162(h0, h1);
                        *(__nv_bfloat162*)&outL[idx] = __halves2bfloat162(l0, l1);
                    } else {  // mode 2: transposed [b,h,d,s]
                        size_t idx = (((size_t)(bb * NH + hh)) * DH + d) * (size_t)S_stride
                                   + seq_off + sdx;
                        outH[idx] = h0; outL[idx] = l0;
                        outH[idx + S_stride] = h1; outL[idx + S_stride] = l1;
                    }
                }
            }
        }
    }
}

// ============================================================================
// Tensor-core flash attention.
// CTA: 128 q-rows of one (b,h); 8 warps x 16 rows. K/V tiles of 64 keys,
// double-buffered cp.async. Q/K/V/P all bf16 hi/lo (drop lo*lo terms).
// V consumed from transposed layout [b,h,d,s] -> same non-trans ldmatrix
// B-frag pattern as the GEMM. Output: bf16 hi/lo token-major [b,s,dim].
// ============================================================================
#define APITCH   72                          // bf16 elems (144 B rows)
#define ATILE_B  (64 * APITCH * 2)           // 9216
#define ASTAGE_B (4 * ATILE_B)               // 36864: Kh,Kl,Vh,Vl
#define ATTN_SMEM (2 * ASTAGE_B)             // 73728

__device__ __forceinline__ void load_kv(
    uint32_t dst,
    const __nv_bfloat16* __restrict__ Kh_g, const __nv_bfloat16* __restrict__ Kl_g,
    const __nv_bfloat16* __restrict__ Vh_g, const __nv_bfloat16* __restrict__ Vl_g,
    int kt, int tid)
{
#pragma unroll
    for (int j = 0; j < 8; ++j) {
        const int t = j >> 1;
        const int q = (j & 1) * 256 + tid;
        const int r = q >> 3;     // row 0..63
        const int c = q & 7;      // 16B chunk
        const uint32_t da = dst + t * ATILE_B + r * (APITCH * 2) + c * 16;
        if (t == 0)      cp16(da, Kh_g + (size_t)(kt * 64 + r) * 64 + c * 8);
        else if (t == 1) cp16(da, Kl_g + (size_t)(kt * 64 + r) * 64 + c * 8);
        else if (t == 2) cp16(da, Vh_g + (size_t)r * SKK + kt * 64 + c * 8);
        else             cp16(da, Vl_g + (size_t)r * SKK + kt * 64 + c * 8);
    }
}

__global__ void __launch_bounds__(256, 1)
attn_tc(const __nv_bfloat16* __restrict__ Qh, const __nv_bfloat16* __restrict__ Ql,
        const __nv_bfloat16* __restrict__ Kh, const __nv_bfloat16* __restrict__ Kl,
        const __nv_bfloat16* __restrict__ Vth, const __nv_bfloat16* __restrict__ Vtl,
        __nv_bfloat16* __restrict__ Oh, __nv_bfloat16* __restrict__ Ol)
{
    extern __shared__ __align__(128) char smem[];
    const uint32_t sb = (uint32_t)__cvta_generic_to_shared(smem);
    const int tid = threadIdx.x;
    const int wid = tid >> 5, lid = tid & 31;
    const int qt = blockIdx.x, h = blockIdx.y, b = blockIdx.z;

    const __nv_bfloat16* Qgh = Qh + ((size_t)(b * NH + h) * SXX + qt * 128) * DH;
    const __nv_bfloat16* Qgl = Ql + ((size_t)(b * NH + h) * SXX + qt * 128) * DH;
    const __nv_bfloat16* Kgh = Kh + (size_t)(b * NH + h) * SKK * DH;
    const __nv_bfloat16* Kgl = Kl + (size_t)(b * NH + h) * SKK * DH;
    const __nv_bfloat16* Vgh = Vth + (size_t)(b * NH + h) * DH * SKK;
    const __nv_bfloat16* Vgl = Vtl + (size_t)(b * NH + h) * DH * SKK;

    // prefetch K/V tile 0 into stage 0
    load_kv(sb, Kgh, Kgl, Vgh, Vgl, 0, tid);
    asm volatile("cp.async.commit_group;" ::: "memory");
    // stage Q (hi at stage1+0, lo at stage1+18432)
#pragma unroll
    for (int j = 0; j < 4; ++j) {
        const int q = j * 256 + tid;      // 0..1023
        const int r = q >> 3, c = q & 7;  // 128 rows x 8 chunks
        cp16(sb + ASTAGE_B + r * (APITCH * 2) + c * 16, Qgh + (size_t)r * 64 + c * 8);
        cp16(sb + ASTAGE_B + 18432 + r * (APITCH * 2) + c * 16, Qgl + (size_t)r * 64 + c * 8);
    }
    asm volatile("cp.async.commit_group;" ::: "memory");
    asm volatile("cp.async.wait_group 0;" ::: "memory");
    __syncthreads();

    // Q a-frags: 4 kd-steps, hi/lo
    uint32_t qhf[4][4], qlf[4][4];
    const int aRow = lid & 15, aCol = (lid >> 4) * 8;
#pragma unroll
    for (int kd = 0; kd < 4; kd++) {
        const uint32_t ao = (wid * 16 + aRow) * (APITCH * 2) + (kd * 16 + aCol) * 2;
        ldsm_x4(qhf[kd][0], qhf[kd][1], qhf[kd][2], qhf[kd][3], sb + ASTAGE_B + ao);
        ldsm_x4(qlf[kd][0], qlf[kd][1], qlf[kd][2], qlf[kd][3], sb + ASTAGE_B + 18432 + ao);
    }
    __syncthreads();
    // prefetch tile 1 into stage 1 (Q consumed)
    load_kv(sb + ASTAGE_B, Kgh, Kgl, Vgh, Vgl, 1, tid);
    asm volatile("cp.async.commit_group;" ::: "memory");

    float m0 = -1e30f, m1 = -1e30f, l0 = 0.f, l1 = 0.f;
    float oacc[8][4];
#pragma unroll
    for (int dt = 0; dt < 8; dt++)
#pragma unroll
        for (int e = 0; e < 4; e++) oacc[dt][e] = 0.f;

    const int bRow = lid & 7, bCol = ((lid >> 3) & 1) * 8;

#pragma unroll 1
    for (int kt = 0; kt < 32; ++kt) {
        if (kt < 31) asm volatile("cp.async.wait_group 1;" ::: "memory");
        else         asm volatile("cp.async.wait_group 0;" ::: "memory");
        __syncthreads();
        const uint32_t st = sb + (kt & 1) * ASTAGE_B;

        // ---- S = Q @ K^T ----
        float sc[8][4];
#pragma unroll
        for (int nt = 0; nt < 8; nt++)
#pragma unroll
            for (int e = 0; e < 4; e++) sc[nt][e] = 0.f;

#pragma unroll
        for (int kd = 0; kd < 4; kd++) {
#pragma unroll
            for (int nt = 0; nt < 8; nt++) {
                const uint32_t bo = (nt * 8 + bRow) * (APITCH * 2) + (kd * 16 + bCol) * 2;
                uint32_t kh2[2], kl2[2];
                ldsm_x2(kh2[0], kh2[1], st + bo);
                ldsm_x2(kl2[0], kl2[1], st + ATILE_B + bo);
                mma_bf16(sc[nt], qhf[kd], kh2);
                mma_bf16(sc[nt], qlf[kd], kh2);
                mma_bf16(sc[nt], qhf[kd], kl2);
            }
        }

        // ---- online softmax (rows r0 = lid>>2, r1 = r0+8) ----
        float mx0 = -1e30f, mx1 = -1e30f;
#pragma unroll
        for (int nt = 0; nt < 8; nt++) {
            mx0 = fmaxf(mx0, fmaxf(sc[nt][0], sc[nt][1]));
            mx1 = fmaxf(mx1, fmaxf(sc[nt][2], sc[nt][3]));
        }
        mx0 = fmaxf(mx0, __shfl_xor_sync(0xffffffffu, mx0, 1));
        mx0 = fmaxf(mx0, __shfl_xor_sync(0xffffffffu, mx0, 2));
        mx1 = fmaxf(mx1, __shfl_xor_sync(0xffffffffu, mx1, 1));
        mx1 = fmaxf(mx1, __shfl_xor_sync(0xffffffffu, mx1, 2));
        const float mn0 = fmaxf(m0, mx0), mn1 = fmaxf(m1, mx1);
        const float al0 = __expf(m0 - mn0), al1 = __expf(m1 - mn1);
        m0 = mn0; m1 = mn1;
        float rs0 = 0.f, rs1 = 0.f;
#pragma unroll
        for (int nt = 0; nt < 8; nt++) {
            sc[nt][0] = __expf(sc[nt][0] - m0);
            sc[nt][1] = __expf(sc[nt][1] - m0);
            sc[nt][2] = __expf(sc[nt][2] - m1);
            sc[nt][3] = __expf(sc[nt][3] - m1);
            rs0 += sc[nt][0] + sc[nt][1];
            rs1 += sc[nt][2] + sc[nt][3];
        }
        rs0 += __shfl_xor_sync(0xffffffffu, rs0, 1);
        rs0 += __shfl_xor_sync(0xffffffffu, rs0, 2);
        rs1 += __shfl_xor_sync(0xffffffffu, rs1, 1);
        rs1 += __shfl_xor_sync(0xffffffffu, rs1, 2);
        l0 = l0 * al0 + rs0;
        l1 = l1 * al1 + rs1;
#pragma unroll
        for (int dt = 0; dt < 8; dt++) {
            oacc[dt][0] *= al0; oacc[dt][1] *= al0;
            oacc[dt][2] *= al1; oacc[dt][3] *= al1;
        }

        // ---- O += P @ V (V transposed in smem: rows=d, cols=s) ----
#pragma unroll
        for (int ks = 0; ks < 4; ks++) {
            // P a-frags from S c-frags (tiles 2ks, 2ks+1), hi/lo split
            float p0 = sc[2 * ks][0],     p1 = sc[2 * ks][1];
            float p2 = sc[2 * ks][2],     p3 = sc[2 * ks][3];
            float p4 = sc[2 * ks + 1][0], p5 = sc[2 * ks + 1][1];
            float p6 = sc[2 * ks + 1][2], p7 = sc[2 * ks + 1][3];
            uint32_t pha[4], pla[4];
            pha[0] = pack_bf16(p0, p1); pha[1] = pack_bf16(p2, p3);
            pha[2] = pack_bf16(p4, p5); pha[3] = pack_bf16(p6, p7);
            float r0v = p0 - __bfloat162float(__float2bfloat16(p0));
            float r1v = p1 - __bfloat162float(__float2bfloat16(p1));
            float r2v = p2 - __bfloat162float(__float2bfloat16(p2));
            float r3v = p3 - __bfloat162float(__float2bfloat16(p3));
            float r4v = p4 - __bfloat162float(__float2bfloat16(p4));
            float r5v = p5 - __bfloat162float(__float2bfloat16(p5));
            float r6v = p6 - __bfloat162float(__float2bfloat16(p6));
            float r7v = p7 - __bfloat162float(__float2bfloat16(p7));
            pla[0] = pack_bf16(r0v, r1v); pla[1] = pack_bf16(r2v, r3v);
            pla[2] = pack_bf16(r4v, r5v); pla[3] = pack_bf16(r6v, r7v);
#pragma unroll
            for (int dt = 0; dt < 8; dt++) {
                const uint32_t vo = (dt * 8 + bRow) * (APITCH * 2) + (ks * 16 + bCol) * 2;
                uint32_t vh2[2], vl2[2];
                ldsm_x2(vh2[0], vh2[1], st + 2 * ATILE_B + vo);
                ldsm_x2(vl2[0], vl2[1], st + 3 * ATILE_B + vo);
                mma_bf16(oacc[dt], pha, vh2);
                mma_bf16(oacc[dt], pla, vh2);
                mma_bf16(oacc[dt], pha, vl2);
            }
        }

        __syncthreads();
        if (kt + 2 < 32) {
            load_kv(sb + (kt & 1) * ASTAGE_B, Kgh, Kgl, Vgh, Vgl, kt + 2, tid);
            asm volatile("cp.async.commit_group;" ::: "memory");
        }
    }

    // ---- epilogue: O / l, bf16 hi/lo, token-major [b,s,dim] ----
    const float inv0 = 1.f / l0, inv1 = 1.f / l1;
    const int row0 = qt * 128 + wid * 16 + (lid >> 2);
    const int row1 = row0 + 8;
    const int lc = (lid & 3) * 2;
#pragma unroll
    for (int dt = 0; dt < 8; dt++) {
        const int col = h * 64 + dt * 8 + lc;
        {
            const float v0 = oacc[dt][0] * inv0, v1 = oacc[dt][1] * inv0;
            const __nv_bfloat16 h0 = __float2bfloat16(v0);
            const __nv_bfloat16 e0 = __float2bfloat16(v0 - __bfloat162float(h0));
            const __nv_bfloat16 h1 = __float2bfloat16(v1);
            const __nv_bfloat16 e1 = __float2bfloat16(v1 - __bfloat162float(h1));
            const size_t i0 = ((size_t)b * SXX + row0) * DIMN + col;
            *(__nv_bfloat162*)&Oh[i0] = __halves2bfloat162(h0, h1);
            *(__nv_bfloat162*)&Ol[i0] = __halves2bfloat162(e0, e1);
        }
        {
            const float v0 = oacc[dt][2] * inv1, v1 = oacc[dt][3] * inv1;
            const __nv_bfloat16 h0 = __float2bfloat16(v0);
            const __nv_bfloat16 e0 = __float2bfloat16(v0 - __bfloat162float(h0));
            const __nv_bfloat16 h1 = __float2bfloat16(v1);
            const __nv_bfloat16 e1 = __float2bfloat16(v1 - __bfloat162float(h1));
            const size_t i1 = ((size_t)b * SXX + row1) * DIMN + col;
            *(__nv_bfloat162*)&Oh[i1] = __halves2bfloat162(h0, h1);
            *(__nv_bfloat162*)&Ol[i1] = __halves2bfloat162(e0, e1);
        }
    }
}

// ============================================================================
// launch
// ============================================================================
extern "C" void kernel_launch(void* const* d_in, const int* in_sizes, int n_in,
                              void* d_out, int out_size)
{
    const float* x     = (const float*)d_in[0];
    const float* y     = (const float*)d_in[1];
    const float* W_Kx  = (const float*)d_in[2];
    const float* b_Kx  = (const float*)d_in[3];
    const float* W_Qx  = (const float*)d_in[4];
    const float* b_Qx  = (const float*)d_in[5];
    const float* W_Vx  = (const float*)d_in[6];
    const float* b_Vx  = (const float*)d_in[7];
    const float* W_Ky  = (const float*)d_in[8];
    const float* b_Ky  = (const float*)d_in[9];
    const float* W_Vy  = (const float*)d_in[10];
    const float* b_Vy  = (const float*)d_in[11];
    const float* W_out = (const float*)d_in[12];
    const float* b_out = (const float*)d_in[13];
    float* out = (float*)d_out;

    __nv_bfloat16 *xh, *xl, *yh, *yl, *Wh, *Wl;
    __nv_bfloat16 *Qhp, *Qlp, *Khp, *Klp, *Vhp, *Vlp, *Ohp, *Olp;
    cudaGetSymbolAddress((void**)&xh, g_xh);   cudaGetSymbolAddress((void**)&xl, g_xl);
    cudaGetSymbolAddress((void**)&yh, g_yh);   cudaGetSymbolAddress((void**)&yl, g_yl);
    cudaGetSymbolAddress((void**)&Wh, g_Wh);   cudaGetSymbolAddress((void**)&Wl, g_Wl);
    cudaGetSymbolAddress((void**)&Qhp, g_Qh);  cudaGetSymbolAddress((void**)&Qlp, g_Ql);
    cudaGetSymbolAddress((void**)&Khp, g_Kh);  cudaGetSymbolAddress((void**)&Klp, g_Kl);
    cudaGetSymbolAddress((void**)&Vhp, g_Vth); cudaGetSymbolAddress((void**)&Vlp, g_Vtl);
    cudaGetSymbolAddress((void**)&Ohp, g_Oh);  cudaGetSymbolAddress((void**)&Olp, g_Ol);

    split_kernel<<<4096, 256>>>(x, xh, xl, 1048576);
    split_kernel<<<4096, 256>>>(y, yh, yl, 1048576);
    const float* srcW[6] = {W_Kx, W_Qx, W_Vx, W_Ky, W_Vy, W_out};
    for (int i = 0; i < 6; i++)
        split_kernel<<<1024, 256>>>(srcW[i], Wh + (size_t)i * 1048576,
                                    Wl + (size_t)i * 1048576, 262144);

    cudaFuncSetAttribute(gemm_tc, cudaFuncAttributeMaxDynamicSharedMemorySize, GEMM_SMEM);
    const dim3 gGrid(8, 32);
#define WHI(i) (Wh + (size_t)(i) * 1048576)
#define WLO(i) (Wl + (size_t)(i) * 1048576)
    // Q (scaled by 1/sqrt(Dh)), K, V (transposed) straight to bf16 hi/lo
    gemm_tc<<<gGrid, 256, GEMM_SMEM>>>(xh, xl, WHI(1), WLO(1), b_Qx, nullptr, Qhp, Qlp, 1, SXX, 0, 0.125f);
    gemm_tc<<<gGrid, 256, GEMM_SMEM>>>(xh, xl, WHI(0), WLO(0), b_Kx, nullptr, Khp, Klp, 1, SKK, 0, 1.f);
    gemm_tc<<<gGrid, 256, GEMM_SMEM>>>(yh, yl, WHI(3), WLO(3), b_Ky, nullptr, Khp, Klp, 1, SKK, SXX, 1.f);
    gemm_tc<<<gGrid, 256, GEMM_SMEM>>>(xh, xl, WHI(2), WLO(2), b_Vx, nullptr, Vhp, Vlp, 2, SKK, 0, 1.f);
    gemm_tc<<<gGrid, 256, GEMM_SMEM>>>(yh, yl, WHI(4), WLO(4), b_Vy, nullptr, Vhp, Vlp, 2, SKK, SXX, 1.f);

    cudaFuncSetAttribute(attn_tc, cudaFuncAttributeMaxDynamicSharedMemorySize, ATTN_SMEM);
    attn_tc<<<dim3(8, 16, 4), 256, ATTN_SMEM>>>(Qhp, Qlp, Khp, Klp, Vhp, Vlp, Ohp, Olp);

    gemm_tc<<<gGrid, 256, GEMM_SMEM>>>(Ohp, Olp, WHI(5), WLO(5), b_out, out, nullptr, nullptr, 0, 0, 0, 1.f);
}

// round 6
// speedup vs baseline: 3.0909x; 1.0157x over previous
#include <cuda_runtime.h>
#include <cuda_bf16.h>
#include <cstdint>

#define DIMN 1024
#define NH   16
#define DH   64
#define NB   4
#define SXX  1024
#define SKK  2048   // Sx + Sy

// ---- scratch (static device allocations are allowed) ----
__device__ __nv_bfloat16 g_xh[4194304], g_xl[4194304];
__device__ __nv_bfloat16 g_yh[4194304], g_yl[4194304];
// weight slots: 0=Qx 1=Kx 2=Vx 3=Ky 4=Vy 5=out (contiguous for fused N)
__device__ __nv_bfloat16 g_Wh[6 * 1048576], g_Wl[6 * 1048576];
__device__ float g_bias[6 * 1024];
__device__ __nv_bfloat16 g_Qh[4194304],  g_Ql[4194304];   // [b,h,s,d]
__device__ __nv_bfloat16 g_Kh[8388608],  g_Kl[8388608];   // [b,h,s,d]
__device__ __nv_bfloat16 g_Vth[8388608], g_Vtl[8388608];  // [b,h,d,s]
__device__ __nv_bfloat16 g_Oh[4194304],  g_Ol[4194304];   // [b,s,dim]

// ============================================================================
// helpers (sm_80-era PTX only — ptxas target is plain sm_103, no tcgen05/TMA)
// ============================================================================
__device__ __forceinline__ void cp16(uint32_t s, const void* g) {
    asm volatile("cp.async.cg.shared.global [%0], [%1], 16;"
                 :: "r"(s), "l"(__cvta_generic_to_global(g)) : "memory");
}
__device__ __forceinline__ void ldsm_x4(uint32_t& r0, uint32_t& r1,
                                        uint32_t& r2, uint32_t& r3, uint32_t a) {
    asm volatile("ldmatrix.sync.aligned.m8n8.x4.shared.b16 {%0,%1,%2,%3}, [%4];"
                 : "=r"(r0), "=r"(r1), "=r"(r2), "=r"(r3) : "r"(a));
}
__device__ __forceinline__ void ldsm_x2(uint32_t& r0, uint32_t& r1, uint32_t a) {
    asm volatile("ldmatrix.sync.aligned.m8n8.x2.shared.b16 {%0,%1}, [%2];"
                 : "=r"(r0), "=r"(r1) : "r"(a));
}
__device__ __forceinline__ void mma_bf16(float* c, const uint32_t* a, const uint32_t* b) {
    asm volatile(
        "mma.sync.aligned.m16n8k16.row.col.f32.bf16.bf16.f32 "
        "{%0,%1,%2,%3}, {%4,%5,%6,%7}, {%8,%9}, {%0,%1,%2,%3};"
        : "+f"(c[0]), "+f"(c[1]), "+f"(c[2]), "+f"(c[3])
        : "r"(a[0]), "r"(a[1]), "r"(a[2]), "r"(a[3]), "r"(b[0]), "r"(b[1]));
}
__device__ __forceinline__ uint32_t pack_bf16(float v0, float v1) {
    uint32_t r;
    asm("cvt.rn.bf16x2.f32 %0, %1, %2;" : "=r"(r) : "f"(v1), "f"(v0));
    return r;
}

// ============================================================================
// split fp32 -> bf16 hi + lo
// ============================================================================
__device__ __forceinline__ void split4(float4 v, __nv_bfloat16* hi, __nv_bfloat16* lo,
                                       size_t i2) {
    __nv_bfloat16 h0 = __float2bfloat16(v.x), h1 = __float2bfloat16(v.y);
    __nv_bfloat16 h2 = __float2bfloat16(v.z), h3 = __float2bfloat16(v.w);
    __nv_bfloat16 l0 = __float2bfloat16(v.x - __bfloat162float(h0));
    __nv_bfloat16 l1 = __float2bfloat16(v.y - __bfloat162float(h1));
    __nv_bfloat16 l2 = __float2bfloat16(v.z - __bfloat162float(h2));
    __nv_bfloat16 l3 = __float2bfloat16(v.w - __bfloat162float(h3));
    ((__nv_bfloat162*)hi)[i2]     = __halves2bfloat162(h0, h1);
    ((__nv_bfloat162*)hi)[i2 + 1] = __halves2bfloat162(h2, h3);
    ((__nv_bfloat162*)lo)[i2]     = __halves2bfloat162(l0, l1);
    ((__nv_bfloat162*)lo)[i2 + 1] = __halves2bfloat162(l2, l3);
}

__global__ void __launch_bounds__(256)
split_kernel(const float* __restrict__ in, __nv_bfloat16* __restrict__ hi,
             __nv_bfloat16* __restrict__ lo, int n4)
{
    int i = blockIdx.x * 256 + threadIdx.x;
    if (i >= n4) return;
    split4(((const float4*)in)[i], hi, lo, 2 * (size_t)i);
}

// all six weights in one launch; grid 6144 x 256
__global__ void __launch_bounds__(256)
split6_kernel(const float* s0, const float* s1, const float* s2,
              const float* s3, const float* s4, const float* s5,
              __nv_bfloat16* __restrict__ hi, __nv_bfloat16* __restrict__ lo)
{
    int i = blockIdx.x * 256 + threadIdx.x;    // 0..1572863
    int slot = i >> 18, j = i & 262143;
    const float* src = (slot == 0) ? s0 : (slot == 1) ? s1 : (slot == 2) ? s2
                     : (slot == 3) ? s3 : (slot == 4) ? s4 : s5;
    split4(((const float4*)src)[j], hi, lo, 2 * (size_t)i);
}

__global__ void __launch_bounds__(256)
bias_concat(const float* b0, const float* b1, const float* b2,
            const float* b3, const float* b4, const float* b5, float* dst)
{
    int i = blockIdx.x * 256 + threadIdx.x;    // 0..6143
    int slot = i >> 10, j = i & 1023;
    const float* src = (slot == 0) ? b0 : (slot == 1) ? b1 : (slot == 2) ? b2
                     : (slot == 3) ? b3 : (slot == 4) ? b4 : b5;
    dst[i] = src[j];
}

// ============================================================================
// shared 128x128xK=1024 hi/lo mainloop: 3-stage cp.async, 1 sync per chunk
// ============================================================================
#define PITCH    40
#define TILE_B   (128 * PITCH * 2)           // 10240 B
#define STAGE_B  (4 * TILE_B)                // 40960 B
#define GEMM_SMEM (3 * STAGE_B)              // 122880 B

__device__ __forceinline__ void load_stage(
    uint32_t sbase,
    const __nv_bfloat16* __restrict__ Ah, const __nv_bfloat16* __restrict__ Al,
    const __nv_bfloat16* __restrict__ Bh, const __nv_bfloat16* __restrict__ Bl,
    int mBase, int nBase, int k0, int tid)
{
    const __nv_bfloat16* srcs[4];
    srcs[0] = Ah + (size_t)mBase * 1024 + k0;
    srcs[1] = Al + (size_t)mBase * 1024 + k0;
    srcs[2] = Bh + (size_t)nBase * 1024 + k0;
    srcs[3] = Bl + (size_t)nBase * 1024 + k0;
#pragma unroll
    for (int j = 0; j < 8; ++j) {
        const int t = j >> 1;
        const int q = (j & 1) * 256 + tid;
        const int r = q >> 2;
        const int c = q & 3;
        cp16(sbase + t * TILE_B + r * (PITCH * 2) + c * 16,
             srcs[t] + (size_t)r * 1024 + c * 8);
    }
}

__device__ __forceinline__ void mainloop128(
    uint32_t sb,
    const __nv_bfloat16* __restrict__ Ah, const __nv_bfloat16* __restrict__ Al,
    const __nv_bfloat16* __restrict__ Bh, const __nv_bfloat16* __restrict__ Bl,
    int mBase, int nBase, int tid, int wid, int lid, float acc[4][4][4])
{
    const int wm = (wid >> 2) * 64;
    const int wn = (wid & 3) * 32;
    const int aRow = lid & 15, aCol = (lid >> 4) * 8;
    const int bRow = lid & 7,  bCol = ((lid >> 3) & 1) * 8;

    load_stage(sb, Ah, Al, Bh, Bl, mBase, nBase, 0, tid);
    asm volatile("cp.async.commit_group;" ::: "memory");
    load_stage(sb + STAGE_B, Ah, Al, Bh, Bl, mBase, nBase, 32, tid);
    asm volatile("cp.async.commit_group;" ::: "memory");

    for (int i = 0; i < 32; ++i) {
        if (i + 1 < 32) asm volatile("cp.async.wait_group 1;" ::: "memory");
        else            asm volatile("cp.async.wait_group 0;" ::: "memory");
        __syncthreads();
        if (i + 2 < 32) {   // stage (i+2)%3 was last read at iter i-1 -> safe
            load_stage(sb + ((i + 2) % 3) * STAGE_B, Ah, Al, Bh, Bl,
                       mBase, nBase, (i + 2) * 32, tid);
            asm volatile("cp.async.commit_group;" ::: "memory");
        }

        const uint32_t st = sb + (i % 3) * STAGE_B;
        const uint32_t sAh = st, sAl = st + TILE_B;
        const uint32_t sBh = st + 2 * TILE_B, sBl = st + 3 * TILE_B;

#pragma unroll
        for (int kk = 0; kk < 32; kk += 16) {
            uint32_t ah[4][4], al[4][4], bh[4][2], bl[4][2];
#pragma unroll
            for (int mt = 0; mt < 4; mt++) {
                const uint32_t ao = (wm + mt * 16 + aRow) * (PITCH * 2) + (kk + aCol) * 2;
                ldsm_x4(ah[mt][0], ah[mt][1], ah[mt][2], ah[mt][3], sAh + ao);
                ldsm_x4(al[mt][0], al[mt][1], al[mt][2], al[mt][3], sAl + ao);
            }
#pragma unroll
            for (int nt = 0; nt < 4; nt++) {
                const uint32_t bo = (wn + nt * 8 + bRow) * (PITCH * 2) + (kk + bCol) * 2;
                ldsm_x2(bh[nt][0], bh[nt][1], sBh + bo);
                ldsm_x2(bl[nt][0], bl[nt][1], sBl + bo);
            }
#pragma unroll
            for (int mt = 0; mt < 4; mt++)
#pragma unroll
                for (int nt = 0; nt < 4; nt++) {
                    mma_bf16(acc[mt][nt], ah[mt], bh[nt]);
                    mma_bf16(acc[mt][nt], al[mt], bh[nt]);
                    mma_bf16(acc[mt][nt], ah[mt], bl[nt]);
                }
        }
    }
}

// ============================================================================
// fused projection GEMM: x -> {Q,K,V} (is_y=0, grid.x=24) or
//                        y -> {Ky,Vy} (is_y=1, grid.x=16)
// weight/bias column space is the concat slot space.
// ============================================================================
__global__ void __launch_bounds__(256, 1)
proj_tc(const __nv_bfloat16* __restrict__ Ah, const __nv_bfloat16* __restrict__ Al,
        const __nv_bfloat16* __restrict__ Wh, const __nv_bfloat16* __restrict__ Wl,
        const float* __restrict__ biasC,
        __nv_bfloat16* __restrict__ Qh, __nv_bfloat16* __restrict__ Ql,
        __nv_bfloat16* __restrict__ Kh, __nv_bfloat16* __restrict__ Kl,
        __nv_bfloat16* __restrict__ Vh, __nv_bfloat16* __restrict__ Vl,
        int is_y)
{
    extern __shared__ __align__(128) char smem[];
    const uint32_t sb = (uint32_t)__cvta_generic_to_shared(smem);
    const int tid = threadIdx.x, wid = tid >> 5, lid = tid & 31;
    const int mBase = blockIdx.y * 128;
    const int nBase = blockIdx.x * 128;          // global concat column

    float acc[4][4][4];
#pragma unroll
    for (int mt = 0; mt < 4; mt++)
#pragma unroll
        for (int nt = 0; nt < 4; nt++)
#pragma unroll
            for (int e = 0; e < 4; e++) acc[mt][nt][e] = 0.f;

    mainloop128(sb, Ah, Al, Wh, Wl, mBase, nBase, tid, wid, lid, acc);

    // per-CTA uniform output selection (nBase group is 1024-aligned x 128 wide)
    const int type = (nBase >> 10) + is_y;       // 0=Q 1=K 2=V
    const float scale = (type == 0) ? 0.125f : 1.f;
    __nv_bfloat16 *oH, *oL;
    int Sst, mode;
    if (type == 0)      { oH = Qh; oL = Ql; Sst = SXX; mode = 1; }
    else if (type == 1) { oH = Kh; oL = Kl; Sst = SKK; mode = 1; }
    else                { oH = Vh; oL = Vl; Sst = SKK; mode = 2; }
    const int seq_off = is_y ? SXX : 0;
    const int wm = (wid >> 2) * 64, wn = (wid & 3) * 32;
    const int lr = lid >> 2, lc = (lid & 3) * 2;

#pragma unroll
    for (int mt = 0; mt < 4; mt++) {
#pragma unroll
        for (int half = 0; half < 2; half++) {
            const int m  = mBase + wm + mt * 16 + half * 8 + lr;
            const int bb = m >> 10, sdx = m & 1023;
#pragma unroll
            for (int nt = 0; nt < 4; nt++) {
                const int n = nBase + wn + nt * 8 + lc;
                const float v0 = (acc[mt][nt][half * 2 + 0] + biasC[n])     * scale;
                const float v1 = (acc[mt][nt][half * 2 + 1] + biasC[n + 1]) * scale;
                const __nv_bfloat16 h0 = __float2bfloat16(v0);
                const __nv_bfloat16 l0 = __float2bfloat16(v0 - __bfloat162float(h0));
                const __nv_bfloat16 h1 = __float2bfloat16(v1);
                const __nv_bfloat16 l1 = __float2bfloat16(v1 - __bfloat162float(h1));
                const int ncol = n & 1023;
                const int hh = ncol >> 6, d = ncol & 63;
                if (mode == 1) {
                    size_t idx = (((size_t)(bb * NH + hh)) * Sst + seq_off + sdx) * DH + d;
                    *(__nv_bfloat162*)&oH[idx] = __halves2bfloat162(h0, h1);
                    *(__nv_bfloat162*)&oL[idx] = __halves2bfloat162(l0, l1);
                } else {    // transposed [b,h,d,s]
                    size_t idx = (((size_t)(bb * NH + hh)) * DH + d) * (size_t)Sst
                               + seq_off + sdx;
                    oH[idx] = h0; oL[idx] = l0;
                    oH[idx + Sst] = h1; oL[idx + Sst] = l1;
                }
            }
        }
    }
}

// out projection: fp32 flat [m, 1024]
__global__ void __launch_bounds__(256, 1)
gemm_out(const __nv_bfloat16* __restrict__ Ah, const __nv_bfloat16* __restrict__ Al,
         const __nv_bfloat16* __restrict__ Wh, const __nv_bfloat16* __restrict__ Wl,
         const float* __restrict__ bias, float* __restrict__ outF)
{
    extern __shared__ __align__(128) char smem[];
    const uint32_t sb = (uint32_t)__cvta_generic_to_shared(smem);
    const int tid = threadIdx.x, wid = tid >> 5, lid = tid & 31;
    const int mBase = blockIdx.y * 128;
    const int nBase = blockIdx.x * 128;

    float acc[4][4][4];
#pragma unroll
    for (int mt = 0; mt < 4; mt++)
#pragma unroll
        for (int nt = 0; nt < 4; nt++)
#pragma unroll
            for (int e = 0; e < 4; e++) acc[mt][nt][e] = 0.f;

    mainloop128(sb, Ah, Al, Wh, Wl, mBase, nBase, tid, wid, lid, acc);

    const int wm = (wid >> 2) * 64, wn = (wid & 3) * 32;
    const int lr = lid >> 2, lc = (lid & 3) * 2;
#pragma unroll
    for (int mt = 0; mt < 4; mt++)
#pragma unroll
        for (int half = 0; half < 2; half++) {
            const int m = mBase + wm + mt * 16 + half * 8 + lr;
#pragma unroll
            for (int nt = 0; nt < 4; nt++) {
                const int n = nBase + wn + nt * 8 + lc;
                *(float2*)&outF[(size_t)m * DIMN + n] = make_float2(
                    acc[mt][nt][half * 2 + 0] + bias[n],
                    acc[mt][nt][half * 2 + 1] + bias[n + 1]);
            }
        }
}

// ============================================================================
// tensor-core flash attention, 3-stage KV pipeline, 1 sync per tile
// ============================================================================
#define APITCH   72
#define ATILE_B  (64 * APITCH * 2)           // 9216
#define ASTAGE_B (4 * ATILE_B)               // 36864: Kh,Kl,Vh,Vl
#define ATTN_SMEM (3 * ASTAGE_B)             // 110592

__device__ __forceinline__ void load_kv(
    uint32_t dst,
    const __nv_bfloat16* __restrict__ Kh_g, const __nv_bfloat16* __restrict__ Kl_g,
    const __nv_bfloat16* __restrict__ Vh_g, const __nv_bfloat16* __restrict__ Vl_g,
    int kt, int tid)
{
#pragma unroll
    for (int j = 0; j < 8; ++j) {
        const int t = j >> 1;
        const int q = (j & 1) * 256 + tid;
        const int r = q >> 3, c = q & 7;
        const uint32_t da = dst + t * ATILE_B + r * (APITCH * 2) + c * 16;
        if (t == 0)      cp16(da, Kh_g + (size_t)(kt * 64 + r) * 64 + c * 8);
        else if (t == 1) cp16(da, Kl_g + (size_t)(kt * 64 + r) * 64 + c * 8);
        else if (t == 2) cp16(da, Vh_g + (size_t)r * SKK + kt * 64 + c * 8);
        else             cp16(da, Vl_g + (size_t)r * SKK + kt * 64 + c * 8);
    }
}

__global__ void __launch_bounds__(256, 1)
attn_tc(const __nv_bfloat16* __restrict__ Qh, const __nv_bfloat16* __restrict__ Ql,
        const __nv_bfloat16* __restrict__ Kh, const __nv_bfloat16* __restrict__ Kl,
        const __nv_bfloat16* __restrict__ Vth, const __nv_bfloat16* __restrict__ Vtl,
        __nv_bfloat16* __restrict__ Oh, __nv_bfloat16* __restrict__ Ol)
{
    extern __shared__ __align__(128) char smem[];
    const uint32_t sb = (uint32_t)__cvta_generic_to_shared(smem);
    const int tid = threadIdx.x, wid = tid >> 5, lid = tid & 31;
    const int qt = blockIdx.x, h = blockIdx.y, b = blockIdx.z;

    const __nv_bfloat16* Qgh = Qh + ((size_t)(b * NH + h) * SXX + qt * 128) * DH;
    const __nv_bfloat16* Qgl = Ql + ((size_t)(b * NH + h) * SXX + qt * 128) * DH;
    const __nv_bfloat16* Kgh = Kh + (size_t)(b * NH + h) * SKK * DH;
    const __nv_bfloat16* Kgl = Kl + (size_t)(b * NH + h) * SKK * DH;
    const __nv_bfloat16* Vgh = Vth + (size_t)(b * NH + h) * DH * SKK;
    const __nv_bfloat16* Vgl = Vtl + (size_t)(b * NH + h) * DH * SKK;

    // prologue: kv0 -> s0, kv1 -> s1, Q -> s2 (consumed to regs, then reused)
    load_kv(sb, Kgh, Kgl, Vgh, Vgl, 0, tid);
    asm volatile("cp.async.commit_group;" ::: "memory");
    load_kv(sb + ASTAGE_B, Kgh, Kgl, Vgh, Vgl, 1, tid);
    asm volatile("cp.async.commit_group;" ::: "memory");
#pragma unroll
    for (int j = 0; j < 4; ++j) {
        const int q = j * 256 + tid;
        const int r = q >> 3, c = q & 7;
        cp16(sb + 2 * ASTAGE_B + r * (APITCH * 2) + c * 16, Qgh + (size_t)r * 64 + c * 8);
        cp16(sb + 2 * ASTAGE_B + 18432 + r * (APITCH * 2) + c * 16,
             Qgl + (size_t)r * 64 + c * 8);
    }
    asm volatile("cp.async.commit_group;" ::: "memory");
    asm volatile("cp.async.wait_group 0;" ::: "memory");
    __syncthreads();

    uint32_t qhf[4][4], qlf[4][4];
    const int aRow = lid & 15, aCol = (lid >> 4) * 8;
#pragma unroll
    for (int kd = 0; kd < 4; kd++) {
        const uint32_t ao = (wid * 16 + aRow) * (APITCH * 2) + (kd * 16 + aCol) * 2;
        ldsm_x4(qhf[kd][0], qhf[kd][1], qhf[kd][2], qhf[kd][3], sb + 2 * ASTAGE_B + ao);
        ldsm_x4(qlf[kd][0], qlf[kd][1], qlf[kd][2], qlf[kd][3],
                sb + 2 * ASTAGE_B + 18432 + ao);
    }

    float m0 = -1e30f, m1 = -1e30f, l0 = 0.f, l1 = 0.f;
    float oacc[8][4];
#pragma unroll
    for (int dt = 0; dt < 8; dt++)
#pragma unroll
        for (int e = 0; e < 4; e++) oacc[dt][e] = 0.f;

    const int bRow = lid & 7, bCol = ((lid >> 3) & 1) * 8;

#pragma unroll 1
    for (int kt = 0; kt < 32; ++kt) {
        if (kt + 1 < 32) asm volatile("cp.async.wait_group 1;" ::: "memory");
        else             asm volatile("cp.async.wait_group 0;" ::: "memory");
        __syncthreads();     // also fences Q-frag reads before s2 is overwritten
        if (kt + 2 < 32) {
            load_kv(sb + ((kt + 2) % 3) * ASTAGE_B, Kgh, Kgl, Vgh, Vgl, kt + 2, tid);
            asm volatile("cp.async.commit_group;" ::: "memory");
        }
        const uint32_t st = sb + (kt % 3) * ASTAGE_B;

        // ---- S = Q @ K^T ----
        float sc[8][4];
#pragma unroll
        for (int nt = 0; nt < 8; nt++)
#pragma unroll
            for (int e = 0; e < 4; e++) sc[nt][e] = 0.f;
#pragma unroll
        for (int kd = 0; kd < 4; kd++) {
#pragma unroll
            for (int nt = 0; nt < 8; nt++) {
                const uint32_t bo = (nt * 8 + bRow) * (APITCH * 2) + (kd * 16 + bCol) * 2;
                uint32_t kh2[2], kl2[2];
                ldsm_x2(kh2[0], kh2[1], st + bo);
                ldsm_x2(kl2[0], kl2[1], st + ATILE_B + bo);
                mma_bf16(sc[nt], qhf[kd], kh2);
                mma_bf16(sc[nt], qlf[kd], kh2);
                mma_bf16(sc[nt], qhf[kd], kl2);
            }
        }

        // ---- online softmax (rows r0 = lid>>2, r1 = r0+8) ----
        float mx0 = -1e30f, mx1 = -1e30f;
#pragma unroll
        for (int nt = 0; nt < 8; nt++) {
            mx0 = fmaxf(mx0, fmaxf(sc[nt][0], sc[nt][1]));
            mx1 = fmaxf(mx1, fmaxf(sc[nt][2], sc[nt][3]));
        }
        mx0 = fmaxf(mx0, __shfl_xor_sync(0xffffffffu, mx0, 1));
        mx0 = fmaxf(mx0, __shfl_xor_sync(0xffffffffu, mx0, 2));
        mx1 = fmaxf(mx1, __shfl_xor_sync(0xffffffffu, mx1, 1));
        mx1 = fmaxf(mx1, __shfl_xor_sync(0xffffffffu, mx1, 2));
        const float mn0 = fmaxf(m0, mx0), mn1 = fmaxf(m1, mx1);
        const float al0 = __expf(m0 - mn0), al1 = __expf(m1 - mn1);
        m0 = mn0; m1 = mn1;
        float rs0 = 0.f, rs1 = 0.f;
#pragma unroll
        for (int nt = 0; nt < 8; nt++) {
            sc[nt][0] = __expf(sc[nt][0] - m0);
            sc[nt][1] = __expf(sc[nt][1] - m0);
            sc[nt][2] = __expf(sc[nt][2] - m1);
            sc[nt][3] = __expf(sc[nt][3] - m1);
            rs0 += sc[nt][0] + sc[nt][1];
            rs1 += sc[nt][2] + sc[nt][3];
        }
        rs0 += __shfl_xor_sync(0xffffffffu, rs0, 1);
        rs0 += __shfl_xor_sync(0xffffffffu, rs0, 2);
        rs1 += __shfl_xor_sync(0xffffffffu, rs1, 1);
        rs1 += __shfl_xor_sync(0xffffffffu, rs1, 2);
        l0 = l0 * al0 + rs0;
        l1 = l1 * al1 + rs1;
#pragma unroll
        for (int dt = 0; dt < 8; dt++) {
            oacc[dt][0] *= al0; oacc[dt][1] *= al0;
            oacc[dt][2] *= al1; oacc[dt][3] *= al1;
        }

        // ---- O += P @ V (V transposed: rows=d, cols=s) ----
#pragma unroll
        for (int ks = 0; ks < 4; ks++) {
            float p0 = sc[2 * ks][0],     p1 = sc[2 * ks][1];
            float p2 = sc[2 * ks][2],     p3 = sc[2 * ks][3];
            float p4 = sc[2 * ks + 1][0], p5 = sc[2 * ks + 1][1];
            float p6 = sc[2 * ks + 1][2], p7 = sc[2 * ks + 1][3];
            uint32_t pha[4], pla[4];
            pha[0] = pack_bf16(p0, p1); pha[1] = pack_bf16(p2, p3);
            pha[2] = pack_bf16(p4, p5); pha[3] = pack_bf16(p6, p7);
            pla[0] = pack_bf16(p0 - __bfloat162float(__float2bfloat16(p0)),
                               p1 - __bfloat162float(__float2bfloat16(p1)));
            pla[1] = pack_bf16(p2 - __bfloat162float(__float2bfloat16(p2)),
                               p3 - __bfloat162float(__float2bfloat16(p3)));
            pla[2] = pack_bf16(p4 - __bfloat162float(__float2bfloat16(p4)),
                               p5 - __bfloat162float(__float2bfloat16(p5)));
            pla[3] = pack_bf16(p6 - __bfloat162float(__float2bfloat16(p6)),
                               p7 - __bfloat162float(__float2bfloat16(p7)));
#pragma unroll
            for (int dt = 0; dt < 8; dt++) {
                const uint32_t vo = (dt * 8 + bRow) * (APITCH * 2) + (ks * 16 + bCol) * 2;
                uint32_t vh2[2], vl2[2];
                ldsm_x2(vh2[0], vh2[1], st + 2 * ATILE_B + vo);
                ldsm_x2(vl2[0], vl2[1], st + 3 * ATILE_B + vo);
                mma_bf16(oacc[dt], pha, vh2);
                mma_bf16(oacc[dt], pla, vh2);
                mma_bf16(oacc[dt], pha, vl2);
            }
        }
    }

    // ---- epilogue ----
    const float inv0 = 1.f / l0, inv1 = 1.f / l1;
    const int row0 = qt * 128 + wid * 16 + (lid >> 2);
    const int row1 = row0 + 8;
    const int lc = (lid & 3) * 2;
#pragma unroll
    for (int dt = 0; dt < 8; dt++) {
        const int col = h * 64 + dt * 8 + lc;
        {
            const float v0 = oacc[dt][0] * inv0, v1 = oacc[dt][1] * inv0;
            const __nv_bfloat16 h0 = __float2bfloat16(v0);
            const __nv_bfloat16 e0 = __float2bfloat16(v0 - __bfloat162float(h0));
            const __nv_bfloat16 h1 = __float2bfloat16(v1);
            const __nv_bfloat16 e1 = __float2bfloat16(v1 - __bfloat162float(h1));
            const size_t i0 = ((size_t)b * SXX + row0) * DIMN + col;
            *(__nv_bfloat162*)&Oh[i0] = __halves2bfloat162(h0, h1);
            *(__nv_bfloat162*)&Ol[i0] = __halves2bfloat162(e0, e1);
        }
        {
            const float v0 = oacc[dt][2] * inv1, v1 = oacc[dt][3] * inv1;
            const __nv_bfloat16 h0 = __float2bfloat16(v0);
            const __nv_bfloat16 e0 = __float2bfloat16(v0 - __bfloat162float(h0));
            const __nv_bfloat16 h1 = __float2bfloat16(v1);
            const __nv_bfloat16 e1 = __float2bfloat16(v1 - __bfloat162float(h1));
            const size_t i1 = ((size_t)b * SXX + row1) * DIMN + col;
            *(__nv_bfloat162*)&Oh[i1] = __halves2bfloat162(h0, h1);
            *(__nv_bfloat162*)&Ol[i1] = __halves2bfloat162(e0, e1);
        }
    }
}

// ============================================================================
// launch
// ============================================================================
extern "C" void kernel_launch(void* const* d_in, const int* in_sizes, int n_in,
                              void* d_out, int out_size)
{
    const float* x     = (const float*)d_in[0];
    const float* y     = (const float*)d_in[1];
    const float* W_Kx  = (const float*)d_in[2];
    const float* b_Kx  = (const float*)d_in[3];
    const float* W_Qx  = (const float*)d_in[4];
    const float* b_Qx  = (const float*)d_in[5];
    const float* W_Vx  = (const float*)d_in[6];
    const float* b_Vx  = (const float*)d_in[7];
    const float* W_Ky  = (const float*)d_in[8];
    const float* b_Ky  = (const float*)d_in[9];
    const float* W_Vy  = (const float*)d_in[10];
    const float* b_Vy  = (const float*)d_in[11];
    const float* W_out = (const float*)d_in[12];
    const float* b_out = (const float*)d_in[13];
    float* out = (float*)d_out;

    __nv_bfloat16 *xh, *xl, *yh, *yl, *Wh, *Wl;
    __nv_bfloat16 *Qhp, *Qlp, *Khp, *Klp, *Vhp, *Vlp, *Ohp, *Olp;
    float* biasC;
    cudaGetSymbolAddress((void**)&xh, g_xh);   cudaGetSymbolAddress((void**)&xl, g_xl);
    cudaGetSymbolAddress((void**)&yh, g_yh);   cudaGetSymbolAddress((void**)&yl, g_yl);
    cudaGetSymbolAddress((void**)&Wh, g_Wh);   cudaGetSymbolAddress((void**)&Wl, g_Wl);
    cudaGetSymbolAddress((void**)&biasC, g_bias);
    cudaGetSymbolAddress((void**)&Qhp, g_Qh);  cudaGetSymbolAddress((void**)&Qlp, g_Ql);
    cudaGetSymbolAddress((void**)&Khp, g_Kh);  cudaGetSymbolAddress((void**)&Klp, g_Kl);
    cudaGetSymbolAddress((void**)&Vhp, g_Vth); cudaGetSymbolAddress((void**)&Vlp, g_Vtl);
    cudaGetSymbolAddress((void**)&Ohp, g_Oh);  cudaGetSymbolAddress((void**)&Olp, g_Ol);

    // splits: x, y, all weights (slot order: Qx,Kx,Vx,Ky,Vy,out), bias concat
    split_kernel<<<4096, 256>>>(x, xh, xl, 1048576);
    split_kernel<<<4096, 256>>>(y, yh, yl, 1048576);
    split6_kernel<<<6144, 256>>>(W_Qx, W_Kx, W_Vx, W_Ky, W_Vy, W_out, Wh, Wl);
    bias_concat<<<24, 256>>>(b_Qx, b_Kx, b_Vx, b_Ky, b_Vy, b_out, biasC);

    cudaFuncSetAttribute(proj_tc,  cudaFuncAttributeMaxDynamicSharedMemorySize, GEMM_SMEM);
    cudaFuncSetAttribute(gemm_out, cudaFuncAttributeMaxDynamicSharedMemorySize, GEMM_SMEM);
    cudaFuncSetAttribute(attn_tc,  cudaFuncAttributeMaxDynamicSharedMemorySize, ATTN_SMEM);

    // fused projections: x -> Q,K,V (N=3072); y -> Ky,Vy (N=2048)
    proj_tc<<<dim3(24, 32), 256, GEMM_SMEM>>>(xh, xl, Wh, Wl, biasC,
                                              Qhp, Qlp, Khp, Klp, Vhp, Vlp, 0);
    proj_tc<<<dim3(16, 32), 256, GEMM_SMEM>>>(yh, yl, Wh + 3 * 1048576ull,
                                              Wl + 3 * 1048576ull, biasC + 3 * 1024,
                                              Qhp, Qlp, Khp, Klp, Vhp, Vlp, 1);

    attn_tc<<<dim3(8, 16, 4), 256, ATTN_SMEM>>>(Qhp, Qlp, Khp, Klp, Vhp, Vlp, Ohp, Olp);

    gemm_out<<<dim3(8, 32), 256, GEMM_SMEM>>>(Ohp, Olp, Wh + 5 * 1048576ull,
                                              Wl + 5 * 1048576ull, b_out, out);
}

// round 7
// speedup vs baseline: 3.3803x; 1.0936x over previous
#include <cuda_runtime.h>
#include <cuda_bf16.h>
#include <cstdint>

#define DIMN 1024
#define NH   16
#define DH   64
#define NB   4
#define SXX  1024
#define SKK  2048   // Sx + Sy

// ---- scratch ----
__device__ __nv_bfloat16 g_xh[4194304], g_xl[4194304];
__device__ __nv_bfloat16 g_yh[4194304], g_yl[4194304];
// weight slots: 0=Qx 1=Kx 2=Vx 3=Ky 4=Vy 5=out
__device__ __nv_bfloat16 g_Wh[6 * 1048576], g_Wl[6 * 1048576];
__device__ float g_bias[6 * 1024];
__device__ __nv_bfloat16 g_Qh[4194304],  g_Ql[4194304];   // [b,h,s,d]
__device__ __nv_bfloat16 g_Kh[8388608],  g_Kl[8388608];   // [b,h,s,d]
__device__ __nv_bfloat16 g_Vth[8388608], g_Vtl[8388608];  // [b,h,d,s]
__device__ __nv_bfloat16 g_Oh[4194304],  g_Ol[4194304];   // [b,s,dim]

// ============================================================================
// helpers (sm_80-era PTX only — ptxas target is plain sm_103)
// ============================================================================
__device__ __forceinline__ void cp16(uint32_t s, const void* g) {
    asm volatile("cp.async.cg.shared.global [%0], [%1], 16;"
                 :: "r"(s), "l"(__cvta_generic_to_global(g)) : "memory");
}
__device__ __forceinline__ void ldsm_x4(uint32_t& r0, uint32_t& r1,
                                        uint32_t& r2, uint32_t& r3, uint32_t a) {
    asm volatile("ldmatrix.sync.aligned.m8n8.x4.shared.b16 {%0,%1,%2,%3}, [%4];"
                 : "=r"(r0), "=r"(r1), "=r"(r2), "=r"(r3) : "r"(a));
}
__device__ __forceinline__ void mma_bf16(float* c, const uint32_t* a, const uint32_t* b) {
    asm volatile(
        "mma.sync.aligned.m16n8k16.row.col.f32.bf16.bf16.f32 "
        "{%0,%1,%2,%3}, {%4,%5,%6,%7}, {%8,%9}, {%0,%1,%2,%3};"
        : "+f"(c[0]), "+f"(c[1]), "+f"(c[2]), "+f"(c[3])
        : "r"(a[0]), "r"(a[1]), "r"(a[2]), "r"(a[3]), "r"(b[0]), "r"(b[1]));
}
__device__ __forceinline__ uint32_t pack_bf16(float v0, float v1) {
    uint32_t r;
    asm("cvt.rn.bf16x2.f32 %0, %1, %2;" : "=r"(r) : "f"(v1), "f"(v0));
    return r;
}

// ============================================================================
// splits
// ============================================================================
__device__ __forceinline__ void split4(float4 v, __nv_bfloat16* hi, __nv_bfloat16* lo,
                                       size_t i2) {
    __nv_bfloat16 h0 = __float2bfloat16(v.x), h1 = __float2bfloat16(v.y);
    __nv_bfloat16 h2 = __float2bfloat16(v.z), h3 = __float2bfloat16(v.w);
    __nv_bfloat16 l0 = __float2bfloat16(v.x - __bfloat162float(h0));
    __nv_bfloat16 l1 = __float2bfloat16(v.y - __bfloat162float(h1));
    __nv_bfloat16 l2 = __float2bfloat16(v.z - __bfloat162float(h2));
    __nv_bfloat16 l3 = __float2bfloat16(v.w - __bfloat162float(h3));
    ((__nv_bfloat162*)hi)[i2]     = __halves2bfloat162(h0, h1);
    ((__nv_bfloat162*)hi)[i2 + 1] = __halves2bfloat162(h2, h3);
    ((__nv_bfloat162*)lo)[i2]     = __halves2bfloat162(l0, l1);
    ((__nv_bfloat162*)lo)[i2 + 1] = __halves2bfloat162(l2, l3);
}

// x and y in one launch (grid 8192)
__global__ void __launch_bounds__(256)
splitxy_kernel(const float* __restrict__ x, const float* __restrict__ y,
               __nv_bfloat16* __restrict__ xh, __nv_bfloat16* __restrict__ xl,
               __nv_bfloat16* __restrict__ yh, __nv_bfloat16* __restrict__ yl)
{
    int i = blockIdx.x * 256 + threadIdx.x;
    if (i < 1048576) split4(((const float4*)x)[i], xh, xl, 2 * (size_t)i);
    else {
        int j = i - 1048576;
        split4(((const float4*)y)[j], yh, yl, 2 * (size_t)j);
    }
}

// all six weights + bias concat in one launch; grid 6168
__global__ void __launch_bounds__(256)
split6_kernel(const float* s0, const float* s1, const float* s2,
              const float* s3, const float* s4, const float* s5,
              const float* b0, const float* b1, const float* b2,
              const float* b3, const float* b4, const float* b5,
              __nv_bfloat16* __restrict__ hi, __nv_bfloat16* __restrict__ lo,
              float* __restrict__ biasC)
{
    if (blockIdx.x >= 6144) {
        int i = (blockIdx.x - 6144) * 256 + threadIdx.x;   // 0..6143
        int slot = i >> 10, j = i & 1023;
        const float* src = (slot == 0) ? b0 : (slot == 1) ? b1 : (slot == 2) ? b2
                         : (slot == 3) ? b3 : (slot == 4) ? b4 : b5;
        biasC[i] = src[j];
        return;
    }
    int i = blockIdx.x * 256 + threadIdx.x;
    int slot = i >> 18, j = i & 262143;
    const float* src = (slot == 0) ? s0 : (slot == 1) ? s1 : (slot == 2) ? s2
                     : (slot == 3) ? s3 : (slot == 4) ? s4 : s5;
    split4(((const float4*)src)[j], hi, lo, 2 * (size_t)i);
}

// ============================================================================
// 128(M) x 256(N) x K=1024 hi/lo mainloop: 3-stage, warp tile 64x64
// smem per stage: A hi/lo 128 rows + B hi/lo 256 rows, 80B pitch
// ============================================================================
#define PITCH    40
#define AREG_B   (128 * PITCH * 2)           // 10240
#define BREG_B   (256 * PITCH * 2)           // 20480
#define STAGE_B  (2 * AREG_B + 2 * BREG_B)   // 61440
#define GEMM_SMEM (3 * STAGE_B)              // 184320

__device__ __forceinline__ void load_stage(
    uint32_t sbase,
    const __nv_bfloat16* __restrict__ Ah, const __nv_bfloat16* __restrict__ Al,
    const __nv_bfloat16* __restrict__ Bh, const __nv_bfloat16* __restrict__ Bl,
    int mBase, int nBase, int k0, int tid)
{
    // 0..511 Ahi, 512..1023 Alo, 1024..2047 Bhi, 2048..3071 Blo
#pragma unroll
    for (int j = 0; j < 12; ++j) {
        const int idx = j * 256 + tid;
        const int c = idx & 3;
        if (idx < 1024) {
            const int r = (idx & 511) >> 2;
            const __nv_bfloat16* src = (idx < 512) ? Ah : Al;
            const uint32_t dst = sbase + ((idx < 512) ? 0 : AREG_B);
            cp16(dst + r * (PITCH * 2) + c * 16,
                 src + (size_t)(mBase + r) * 1024 + k0 + c * 8);
        } else {
            const int q = idx - 1024;
            const int r = (q & 1023) >> 2;
            const __nv_bfloat16* src = (q < 1024) ? Bh : Bl;
            const uint32_t dst = sbase + 2 * AREG_B + ((q < 1024) ? 0 : BREG_B);
            cp16(dst + r * (PITCH * 2) + c * 16,
                 src + (size_t)(nBase + r) * 1024 + k0 + c * 8);
        }
    }
}

__device__ __forceinline__ void mainloop256(
    uint32_t sb,
    const __nv_bfloat16* __restrict__ Ah, const __nv_bfloat16* __restrict__ Al,
    const __nv_bfloat16* __restrict__ Bh, const __nv_bfloat16* __restrict__ Bl,
    int mBase, int nBase, int tid, int wid, int lid, float acc[4][8][4])
{
    const int wm = (wid >> 2) * 64;
    const int wn = (wid & 3) * 64;
    const int aRow = lid & 15, aCol = (lid >> 4) * 8;
    const int bRow = ((lid >> 4) & 1) * 8 + (lid & 7);
    const int bCol = ((lid >> 3) & 1) * 8;

    load_stage(sb, Ah, Al, Bh, Bl, mBase, nBase, 0, tid);
    asm volatile("cp.async.commit_group;" ::: "memory");
    load_stage(sb + STAGE_B, Ah, Al, Bh, Bl, mBase, nBase, 32, tid);
    asm volatile("cp.async.commit_group;" ::: "memory");

    for (int i = 0; i < 32; ++i) {
        if (i + 1 < 32) asm volatile("cp.async.wait_group 1;" ::: "memory");
        else            asm volatile("cp.async.wait_group 0;" ::: "memory");
        __syncthreads();
        if (i + 2 < 32) {
            load_stage(sb + ((i + 2) % 3) * STAGE_B, Ah, Al, Bh, Bl,
                       mBase, nBase, (i + 2) * 32, tid);
            asm volatile("cp.async.commit_group;" ::: "memory");
        }

        const uint32_t st = sb + (i % 3) * STAGE_B;
        const uint32_t sAh = st, sAl = st + AREG_B;
        const uint32_t sBh = st + 2 * AREG_B, sBl = sBh + BREG_B;

#pragma unroll
        for (int kk = 0; kk < 32; kk += 16) {
            uint32_t ah[4][4], al[4][4];
#pragma unroll
            for (int mt = 0; mt < 4; mt++) {
                const uint32_t ao = (wm + mt * 16 + aRow) * (PITCH * 2) + (kk + aCol) * 2;
                ldsm_x4(ah[mt][0], ah[mt][1], ah[mt][2], ah[mt][3], sAh + ao);
                ldsm_x4(al[mt][0], al[mt][1], al[mt][2], al[mt][3], sAl + ao);
            }
#pragma unroll
            for (int ntp = 0; ntp < 4; ntp++) {
                const uint32_t bo = (wn + ntp * 16 + bRow) * (PITCH * 2) + (kk + bCol) * 2;
                uint32_t bh4[4], bl4[4];
                ldsm_x4(bh4[0], bh4[1], bh4[2], bh4[3], sBh + bo);
                ldsm_x4(bl4[0], bl4[1], bl4[2], bl4[3], sBl + bo);
#pragma unroll
                for (int mt = 0; mt < 4; mt++) {
                    mma_bf16(acc[mt][2 * ntp],     ah[mt], &bh4[0]);
                    mma_bf16(acc[mt][2 * ntp],     al[mt], &bh4[0]);
                    mma_bf16(acc[mt][2 * ntp],     ah[mt], &bl4[0]);
                    mma_bf16(acc[mt][2 * ntp + 1], ah[mt], &bh4[2]);
                    mma_bf16(acc[mt][2 * ntp + 1], al[mt], &bh4[2]);
                    mma_bf16(acc[mt][2 * ntp + 1], ah[mt], &bl4[2]);
                }
            }
        }
    }
}

// ============================================================================
// fused projection GEMM (x -> QKV: grid 12x32; y -> KyVy: grid 8x32)
// ============================================================================
__global__ void __launch_bounds__(256, 1)
proj_tc(const __nv_bfloat16* __restrict__ Ah, const __nv_bfloat16* __restrict__ Al,
        const __nv_bfloat16* __restrict__ Wh, const __nv_bfloat16* __restrict__ Wl,
        const float* __restrict__ biasC,
        __nv_bfloat16* __restrict__ Qh, __nv_bfloat16* __restrict__ Ql,
        __nv_bfloat16* __restrict__ Kh, __nv_bfloat16* __restrict__ Kl,
        __nv_bfloat16* __restrict__ Vh, __nv_bfloat16* __restrict__ Vl,
        int is_y)
{
    extern __shared__ __align__(128) char smem[];
    const uint32_t sb = (uint32_t)__cvta_generic_to_shared(smem);
    const int tid = threadIdx.x, wid = tid >> 5, lid = tid & 31;
    const int mBase = blockIdx.y * 128;
    const int nBase = blockIdx.x * 256;

    float acc[4][8][4];
#pragma unroll
    for (int mt = 0; mt < 4; mt++)
#pragma unroll
        for (int nt = 0; nt < 8; nt++)
#pragma unroll
            for (int e = 0; e < 4; e++) acc[mt][nt][e] = 0.f;

    mainloop256(sb, Ah, Al, Wh, Wl, mBase, nBase, tid, wid, lid, acc);

    const int wm = (wid >> 2) * 64, wn = (wid & 3) * 64;
    const int lr = lid >> 2, lc = (lid & 3) * 2;
    // warp's 64-col span is within one slot (nBase 256-aligned, slots 1024-wide)
    const int type0 = ((nBase + wn) >> 10) + is_y;      // 0=Q 1=K 2=V
    const float scale = (type0 == 0) ? 0.125f : 1.f;
    __nv_bfloat16 *oH, *oL;
    int Sst, mode;
    if (type0 == 0)      { oH = Qh; oL = Ql; Sst = SXX; mode = 1; }
    else if (type0 == 1) { oH = Kh; oL = Kl; Sst = SKK; mode = 1; }
    else                 { oH = Vh; oL = Vl; Sst = SKK; mode = 2; }
    const int seq_off = is_y ? SXX : 0;

#pragma unroll
    for (int mt = 0; mt < 4; mt++) {
#pragma unroll
        for (int half = 0; half < 2; half++) {
            const int m  = mBase + wm + mt * 16 + half * 8 + lr;
            const int bb = m >> 10, sdx = m & 1023;
#pragma unroll
            for (int nt = 0; nt < 8; nt++) {
                const int n = nBase + wn + nt * 8 + lc;
                const float v0 = (acc[mt][nt][half * 2 + 0] + biasC[n])     * scale;
                const float v1 = (acc[mt][nt][half * 2 + 1] + biasC[n + 1]) * scale;
                const __nv_bfloat16 h0 = __float2bfloat16(v0);
                const __nv_bfloat16 l0 = __float2bfloat16(v0 - __bfloat162float(h0));
                const __nv_bfloat16 h1 = __float2bfloat16(v1);
                const __nv_bfloat16 l1 = __float2bfloat16(v1 - __bfloat162float(h1));
                const int ncol = n & 1023;
                const int hh = ncol >> 6, d = ncol & 63;
                if (mode == 1) {
                    size_t idx = (((size_t)(bb * NH + hh)) * Sst + seq_off + sdx) * DH + d;
                    *(__nv_bfloat162*)&oH[idx] = __halves2bfloat162(h0, h1);
                    *(__nv_bfloat162*)&oL[idx] = __halves2bfloat162(l0, l1);
                } else {
                    size_t idx = (((size_t)(bb * NH + hh)) * DH + d) * (size_t)Sst
                               + seq_off + sdx;
                    oH[idx] = h0; oL[idx] = l0;
                    oH[idx + Sst] = h1; oL[idx + Sst] = l1;
                }
            }
        }
    }
}

// out projection (grid 4x32): fp32 flat [m, 1024]
__global__ void __launch_bounds__(256, 1)
gemm_out(const __nv_bfloat16* __restrict__ Ah, const __nv_bfloat16* __restrict__ Al,
         const __nv_bfloat16* __restrict__ Wh, const __nv_bfloat16* __restrict__ Wl,
         const float* __restrict__ bias, float* __restrict__ outF)
{
    extern __shared__ __align__(128) char smem[];
    const uint32_t sb = (uint32_t)__cvta_generic_to_shared(smem);
    const int tid = threadIdx.x, wid = tid >> 5, lid = tid & 31;
    const int mBase = blockIdx.y * 128;
    const int nBase = blockIdx.x * 256;

    float acc[4][8][4];
#pragma unroll
    for (int mt = 0; mt < 4; mt++)
#pragma unroll
        for (int nt = 0; nt < 8; nt++)
#pragma unroll
            for (int e = 0; e < 4; e++) acc[mt][nt][e] = 0.f;

    mainloop256(sb, Ah, Al, Wh, Wl, mBase, nBase, tid, wid, lid, acc);

    const int wm = (wid >> 2) * 64, wn = (wid & 3) * 64;
    const int lr = lid >> 2, lc = (lid & 3) * 2;
#pragma unroll
    for (int mt = 0; mt < 4; mt++)
#pragma unroll
        for (int half = 0; half < 2; half++) {
            const int m = mBase + wm + mt * 16 + half * 8 + lr;
#pragma unroll
            for (int nt = 0; nt < 8; nt++) {
                const int n = nBase + wn + nt * 8 + lc;
                *(float2*)&outF[(size_t)m * DIMN + n] = make_float2(
                    acc[mt][nt][half * 2 + 0] + bias[n],
                    acc[mt][nt][half * 2 + 1] + bias[n + 1]);
            }
        }
}

// ============================================================================
// tensor-core flash attention (x4 K/V fragment loads)
// ============================================================================
#define APITCH   72
#define ATILE_B  (64 * APITCH * 2)           // 9216
#define ASTAGE_B (4 * ATILE_B)               // 36864
#define ATTN_SMEM (3 * ASTAGE_B)             // 110592

__device__ __forceinline__ void load_kv(
    uint32_t dst,
    const __nv_bfloat16* __restrict__ Kh_g, const __nv_bfloat16* __restrict__ Kl_g,
    const __nv_bfloat16* __restrict__ Vh_g, const __nv_bfloat16* __restrict__ Vl_g,
    int kt, int tid)
{
#pragma unroll
    for (int j = 0; j < 8; ++j) {
        const int t = j >> 1;
        const int q = (j & 1) * 256 + tid;
        const int r = q >> 3, c = q & 7;
        const uint32_t da = dst + t * ATILE_B + r * (APITCH * 2) + c * 16;
        if (t == 0)      cp16(da, Kh_g + (size_t)(kt * 64 + r) * 64 + c * 8);
        else if (t == 1) cp16(da, Kl_g + (size_t)(kt * 64 + r) * 64 + c * 8);
        else if (t == 2) cp16(da, Vh_g + (size_t)r * SKK + kt * 64 + c * 8);
        else             cp16(da, Vl_g + (size_t)r * SKK + kt * 64 + c * 8);
    }
}

__global__ void __launch_bounds__(256, 1)
attn_tc(const __nv_bfloat16* __restrict__ Qh, const __nv_bfloat16* __restrict__ Ql,
        const __nv_bfloat16* __restrict__ Kh, const __nv_bfloat16* __restrict__ Kl,
        const __nv_bfloat16* __restrict__ Vth, const __nv_bfloat16* __restrict__ Vtl,
        __nv_bfloat16* __restrict__ Oh, __nv_bfloat16* __restrict__ Ol)
{
    extern __shared__ __align__(128) char smem[];
    const uint32_t sb = (uint32_t)__cvta_generic_to_shared(smem);
    const int tid = threadIdx.x, wid = tid >> 5, lid = tid & 31;
    const int qt = blockIdx.x, h = blockIdx.y, b = blockIdx.z;

    const __nv_bfloat16* Qgh = Qh + ((size_t)(b * NH + h) * SXX + qt * 128) * DH;
    const __nv_bfloat16* Qgl = Ql + ((size_t)(b * NH + h) * SXX + qt * 128) * DH;
    const __nv_bfloat16* Kgh = Kh + (size_t)(b * NH + h) * SKK * DH;
    const __nv_bfloat16* Kgl = Kl + (size_t)(b * NH + h) * SKK * DH;
    const __nv_bfloat16* Vgh = Vth + (size_t)(b * NH + h) * DH * SKK;
    const __nv_bfloat16* Vgl = Vtl + (size_t)(b * NH + h) * DH * SKK;

    load_kv(sb, Kgh, Kgl, Vgh, Vgl, 0, tid);
    asm volatile("cp.async.commit_group;" ::: "memory");
    load_kv(sb + ASTAGE_B, Kgh, Kgl, Vgh, Vgl, 1, tid);
    asm volatile("cp.async.commit_group;" ::: "memory");
#pragma unroll
    for (int j = 0; j < 4; ++j) {
        const int q = j * 256 + tid;
        const int r = q >> 3, c = q & 7;
        cp16(sb + 2 * ASTAGE_B + r * (APITCH * 2) + c * 16, Qgh + (size_t)r * 64 + c * 8);
        cp16(sb + 2 * ASTAGE_B + 18432 + r * (APITCH * 2) + c * 16,
             Qgl + (size_t)r * 64 + c * 8);
    }
    asm volatile("cp.async.commit_group;" ::: "memory");
    asm volatile("cp.async.wait_group 0;" ::: "memory");
    __syncthreads();

    uint32_t qhf[4][4], qlf[4][4];
    const int aRow = lid & 15, aCol = (lid >> 4) * 8;
#pragma unroll
    for (int kd = 0; kd < 4; kd++) {
        const uint32_t ao = (wid * 16 + aRow) * (APITCH * 2) + (kd * 16 + aCol) * 2;
        ldsm_x4(qhf[kd][0], qhf[kd][1], qhf[kd][2], qhf[kd][3], sb + 2 * ASTAGE_B + ao);
        ldsm_x4(qlf[kd][0], qlf[kd][1], qlf[kd][2], qlf[kd][3],
                sb + 2 * ASTAGE_B + 18432 + ao);
    }

    float m0 = -1e30f, m1 = -1e30f, l0 = 0.f, l1 = 0.f;
    float oacc[8][4];
#pragma unroll
    for (int dt = 0; dt < 8; dt++)
#pragma unroll
        for (int e = 0; e < 4; e++) oacc[dt][e] = 0.f;

    // x4 B-frag addressing: pairs of 8-row tiles
    const int bRow = ((lid >> 4) & 1) * 8 + (lid & 7);
    const int bCol = ((lid >> 3) & 1) * 8;

#pragma unroll 1
    for (int kt = 0; kt < 32; ++kt) {
        if (kt + 1 < 32) asm volatile("cp.async.wait_group 1;" ::: "memory");
        else             asm volatile("cp.async.wait_group 0;" ::: "memory");
        __syncthreads();
        if (kt + 2 < 32) {
            load_kv(sb + ((kt + 2) % 3) * ASTAGE_B, Kgh, Kgl, Vgh, Vgl, kt + 2, tid);
            asm volatile("cp.async.commit_group;" ::: "memory");
        }
        const uint32_t st = sb + (kt % 3) * ASTAGE_B;

        // ---- S = Q @ K^T ----
        float sc[8][4];
#pragma unroll
        for (int nt = 0; nt < 8; nt++)
#pragma unroll
            for (int e = 0; e < 4; e++) sc[nt][e] = 0.f;
#pragma unroll
        for (int kd = 0; kd < 4; kd++) {
#pragma unroll
            for (int ntp = 0; ntp < 4; ntp++) {
                const uint32_t bo = (ntp * 16 + bRow) * (APITCH * 2) + (kd * 16 + bCol) * 2;
                uint32_t kh4[4], kl4[4];
                ldsm_x4(kh4[0], kh4[1], kh4[2], kh4[3], st + bo);
                ldsm_x4(kl4[0], kl4[1], kl4[2], kl4[3], st + ATILE_B + bo);
                mma_bf16(sc[2 * ntp],     qhf[kd], &kh4[0]);
                mma_bf16(sc[2 * ntp],     qlf[kd], &kh4[0]);
                mma_bf16(sc[2 * ntp],     qhf[kd], &kl4[0]);
                mma_bf16(sc[2 * ntp + 1], qhf[kd], &kh4[2]);
                mma_bf16(sc[2 * ntp + 1], qlf[kd], &kh4[2]);
                mma_bf16(sc[2 * ntp + 1], qhf[kd], &kl4[2]);
            }
        }

        // ---- online softmax ----
        float mx0 = -1e30f, mx1 = -1e30f;
#pragma unroll
        for (int nt = 0; nt < 8; nt++) {
            mx0 = fmaxf(mx0, fmaxf(sc[nt][0], sc[nt][1]));
            mx1 = fmaxf(mx1, fmaxf(sc[nt][2], sc[nt][3]));
        }
        mx0 = fmaxf(mx0, __shfl_xor_sync(0xffffffffu, mx0, 1));
        mx0 = fmaxf(mx0, __shfl_xor_sync(0xffffffffu, mx0, 2));
        mx1 = fmaxf(mx1, __shfl_xor_sync(0xffffffffu, mx1, 1));
        mx1 = fmaxf(mx1, __shfl_xor_sync(0xffffffffu, mx1, 2));
        const float mn0 = fmaxf(m0, mx0), mn1 = fmaxf(m1, mx1);
        const float al0 = __expf(m0 - mn0), al1 = __expf(m1 - mn1);
        m0 = mn0; m1 = mn1;
        float rs0 = 0.f, rs1 = 0.f;
#pragma unroll
        for (int nt = 0; nt < 8; nt++) {
            sc[nt][0] = __expf(sc[nt][0] - m0);
            sc[nt][1] = __expf(sc[nt][1] - m0);
            sc[nt][2] = __expf(sc[nt][2] - m1);
            sc[nt][3] = __expf(sc[nt][3] - m1);
            rs0 += sc[nt][0] + sc[nt][1];
            rs1 += sc[nt][2] + sc[nt][3];
        }
        rs0 += __shfl_xor_sync(0xffffffffu, rs0, 1);
        rs0 += __shfl_xor_sync(0xffffffffu, rs0, 2);
        rs1 += __shfl_xor_sync(0xffffffffu, rs1, 1);
        rs1 += __shfl_xor_sync(0xffffffffu, rs1, 2);
        l0 = l0 * al0 + rs0;
        l1 = l1 * al1 + rs1;
#pragma unroll
        for (int dt = 0; dt < 8; dt++) {
            oacc[dt][0] *= al0; oacc[dt][1] *= al0;
            oacc[dt][2] *= al1; oacc[dt][3] *= al1;
        }

        // ---- O += P @ V ----
#pragma unroll
        for (int ks = 0; ks < 4; ks++) {
            float p0 = sc[2 * ks][0],     p1 = sc[2 * ks][1];
            float p2 = sc[2 * ks][2],     p3 = sc[2 * ks][3];
            float p4 = sc[2 * ks + 1][0], p5 = sc[2 * ks + 1][1];
            float p6 = sc[2 * ks + 1][2], p7 = sc[2 * ks + 1][3];
            uint32_t pha[4], pla[4];
            pha[0] = pack_bf16(p0, p1); pha[1] = pack_bf16(p2, p3);
            pha[2] = pack_bf16(p4, p5); pha[3] = pack_bf16(p6, p7);
            pla[0] = pack_bf16(p0 - __bfloat162float(__float2bfloat16(p0)),
                               p1 - __bfloat162float(__float2bfloat16(p1)));
            pla[1] = pack_bf16(p2 - __bfloat162float(__float2bfloat16(p2)),
                               p3 - __bfloat162float(__float2bfloat16(p3)));
            pla[2] = pack_bf16(p4 - __bfloat162float(__float2bfloat16(p4)),
                               p5 - __bfloat162float(__float2bfloat16(p5)));
            pla[3] = pack_bf16(p6 - __bfloat162float(__float2bfloat16(p6)),
                               p7 - __bfloat162float(__float2bfloat16(p7)));
#pragma unroll
            for (int dtp = 0; dtp < 4; dtp++) {
                const uint32_t vo = (dtp * 16 + bRow) * (APITCH * 2) + (ks * 16 + bCol) * 2;
                uint32_t vh4[4], vl4[4];
                ldsm_x4(vh4[0], vh4[1], vh4[2], vh4[3], st + 2 * ATILE_B + vo);
                ldsm_x4(vl4[0], vl4[1], vl4[2], vl4[3], st + 3 * ATILE_B + vo);
                mma_bf16(oacc[2 * dtp],     pha, &vh4[0]);
                mma_bf16(oacc[2 * dtp],     pla, &vh4[0]);
                mma_bf16(oacc[2 * dtp],     pha, &vl4[0]);
                mma_bf16(oacc[2 * dtp + 1], pha, &vh4[2]);
                mma_bf16(oacc[2 * dtp + 1], pla, &vh4[2]);
                mma_bf16(oacc[2 * dtp + 1], pha, &vl4[2]);
            }
        }
    }

    // ---- epilogue ----
    const float inv0 = 1.f / l0, inv1 = 1.f / l1;
    const int row0 = qt * 128 + wid * 16 + (lid >> 2);
    const int row1 = row0 + 8;
    const int lc = (lid & 3) * 2;
#pragma unroll
    for (int dt = 0; dt < 8; dt++) {
        const int col = h * 64 + dt * 8 + lc;
        {
            const float v0 = oacc[dt][0] * inv0, v1 = oacc[dt][1] * inv0;
            const __nv_bfloat16 h0 = __float2bfloat16(v0);
            const __nv_bfloat16 e0 = __float2bfloat16(v0 - __bfloat162float(h0));
            const __nv_bfloat16 h1 = __float2bfloat16(v1);
            const __nv_bfloat16 e1 = __float2bfloat16(v1 - __bfloat162float(h1));
            const size_t i0 = ((size_t)b * SXX + row0) * DIMN + col;
            *(__nv_bfloat162*)&Oh[i0] = __halves2bfloat162(h0, h1);
            *(__nv_bfloat162*)&Ol[i0] = __halves2bfloat162(e0, e1);
        }
        {
            const float v0 = oacc[dt][2] * inv1, v1 = oacc[dt][3] * inv1;
            const __nv_bfloat16 h0 = __float2bfloat16(v0);
            const __nv_bfloat16 e0 = __float2bfloat16(v0 - __bfloat162float(h0));
            const __nv_bfloat16 h1 = __float2bfloat16(v1);
            const __nv_bfloat16 e1 = __float2bfloat16(v1 - __bfloat162float(h1));
            const size_t i1 = ((size_t)b * SXX + row1) * DIMN + col;
            *(__nv_bfloat162*)&Oh[i1] = __halves2bfloat162(h0, h1);
            *(__nv_bfloat162*)&Ol[i1] = __halves2bfloat162(e0, e1);
        }
    }
}

// ============================================================================
// launch
// ============================================================================
extern "C" void kernel_launch(void* const* d_in, const int* in_sizes, int n_in,
                              void* d_out, int out_size)
{
    const float* x     = (const float*)d_in[0];
    const float* y     = (const float*)d_in[1];
    const float* W_Kx  = (const float*)d_in[2];
    const float* b_Kx  = (const float*)d_in[3];
    const float* W_Qx  = (const float*)d_in[4];
    const float* b_Qx  = (const float*)d_in[5];
    const float* W_Vx  = (const float*)d_in[6];
    const float* b_Vx  = (const float*)d_in[7];
    const float* W_Ky  = (const float*)d_in[8];
    const float* b_Ky  = (const float*)d_in[9];
    const float* W_Vy  = (const float*)d_in[10];
    const float* b_Vy  = (const float*)d_in[11];
    const float* W_out = (const float*)d_in[12];
    const float* b_out = (const float*)d_in[13];
    float* out = (float*)d_out;

    __nv_bfloat16 *xh, *xl, *yh, *yl, *Wh, *Wl;
    __nv_bfloat16 *Qhp, *Qlp, *Khp, *Klp, *Vhp, *Vlp, *Ohp, *Olp;
    float* biasC;
    cudaGetSymbolAddress((void**)&xh, g_xh);   cudaGetSymbolAddress((void**)&xl, g_xl);
    cudaGetSymbolAddress((void**)&yh, g_yh);   cudaGetSymbolAddress((void**)&yl, g_yl);
    cudaGetSymbolAddress((void**)&Wh, g_Wh);   cudaGetSymbolAddress((void**)&Wl, g_Wl);
    cudaGetSymbolAddress((void**)&biasC, g_bias);
    cudaGetSymbolAddress((void**)&Qhp, g_Qh);  cudaGetSymbolAddress((void**)&Qlp, g_Ql);
    cudaGetSymbolAddress((void**)&Khp, g_Kh);  cudaGetSymbolAddress((void**)&Klp, g_Kl);
    cudaGetSymbolAddress((void**)&Vhp, g_Vth); cudaGetSymbolAddress((void**)&Vlp, g_Vtl);
    cudaGetSymbolAddress((void**)&Ohp, g_Oh);  cudaGetSymbolAddress((void**)&Olp, g_Ol);

    splitxy_kernel<<<8192, 256>>>(x, y, xh, xl, yh, yl);
    split6_kernel<<<6168, 256>>>(W_Qx, W_Kx, W_Vx, W_Ky, W_Vy, W_out,
                                 b_Qx, b_Kx, b_Vx, b_Ky, b_Vy, b_out,
                                 Wh, Wl, biasC);

    cudaFuncSetAttribute(proj_tc,  cudaFuncAttributeMaxDynamicSharedMemorySize, GEMM_SMEM);
    cudaFuncSetAttribute(gemm_out, cudaFuncAttributeMaxDynamicSharedMemorySize, GEMM_SMEM);
    cudaFuncSetAttribute(attn_tc,  cudaFuncAttributeMaxDynamicSharedMemorySize, ATTN_SMEM);

    proj_tc<<<dim3(12, 32), 256, GEMM_SMEM>>>(xh, xl, Wh, Wl, biasC,
                                              Qhp, Qlp, Khp, Klp, Vhp, Vlp, 0);
    proj_tc<<<dim3(8, 32), 256, GEMM_SMEM>>>(yh, yl, Wh + 3 * 1048576ull,
                                             Wl + 3 * 1048576ull, biasC + 3 * 1024,
                                             Qhp, Qlp, Khp, Klp, Vhp, Vlp, 1);

    attn_tc<<<dim3(8, 16, 4), 256, ATTN_SMEM>>>(Qhp, Qlp, Khp, Klp, Vhp, Vlp, Ohp, Olp);

    gemm_out<<<dim3(4, 32), 256, GEMM_SMEM>>>(Ohp, Olp, Wh + 5 * 1048576ull,
                                              Wl + 5 * 1048576ull, b_out, out);
}

// round 8
// speedup vs baseline: 3.4370x; 1.0168x over previous
#include <cuda_runtime.h>
#include <cuda_bf16.h>
#include <cstdint>

#define DIMN 1024
#define NH   16
#define DH   64
#define NB   4
#define SXX  1024
#define SKK  2048   // Sx + Sy

// ---- scratch ----
__device__ __nv_bfloat16 g_xh[4194304], g_xl[4194304];
__device__ __nv_bfloat16 g_yh[4194304], g_yl[4194304];
// weight slots: 0=Qx 1=Kx 2=Vx 3=Ky 4=Vy 5=out
__device__ __nv_bfloat16 g_Wh[6 * 1048576], g_Wl[6 * 1048576];
__device__ float g_bias[6 * 1024];
__device__ __nv_bfloat16 g_Qh[4194304],  g_Ql[4194304];   // [b,h,s,d]
__device__ __nv_bfloat16 g_Kh[8388608],  g_Kl[8388608];   // [b,h,s,d]
__device__ __nv_bfloat16 g_Vth[8388608], g_Vtl[8388608];  // [b,h,d,s]
__device__ __nv_bfloat16 g_Oh[4194304],  g_Ol[4194304];   // [b,s,dim]

// ============================================================================
// helpers (sm_80-era PTX only — ptxas target is plain sm_103)
// ============================================================================
__device__ __forceinline__ void cp16(uint32_t s, const void* g) {
    asm volatile("cp.async.cg.shared.global [%0], [%1], 16;"
                 :: "r"(s), "l"(__cvta_generic_to_global(g)) : "memory");
}
__device__ __forceinline__ void ldsm_x4(uint32_t& r0, uint32_t& r1,
                                        uint32_t& r2, uint32_t& r3, uint32_t a) {
    asm volatile("ldmatrix.sync.aligned.m8n8.x4.shared.b16 {%0,%1,%2,%3}, [%4];"
                 : "=r"(r0), "=r"(r1), "=r"(r2), "=r"(r3) : "r"(a));
}
__device__ __forceinline__ void mma_bf16(float* c, const uint32_t* a, const uint32_t* b) {
    asm volatile(
        "mma.sync.aligned.m16n8k16.row.col.f32.bf16.bf16.f32 "
        "{%0,%1,%2,%3}, {%4,%5,%6,%7}, {%8,%9}, {%0,%1,%2,%3};"
        : "+f"(c[0]), "+f"(c[1]), "+f"(c[2]), "+f"(c[3])
        : "r"(a[0]), "r"(a[1]), "r"(a[2]), "r"(a[3]), "r"(b[0]), "r"(b[1]));
}
__device__ __forceinline__ uint32_t pack_bf16(float v0, float v1) {
    uint32_t r;
    asm("cvt.rn.bf16x2.f32 %0, %1, %2;" : "=r"(r) : "f"(v1), "f"(v0));
    return r;
}

// ============================================================================
// splits
// ============================================================================
__device__ __forceinline__ void split4(float4 v, __nv_bfloat16* hi, __nv_bfloat16* lo,
                                       size_t i2) {
    __nv_bfloat16 h0 = __float2bfloat16(v.x), h1 = __float2bfloat16(v.y);
    __nv_bfloat16 h2 = __float2bfloat16(v.z), h3 = __float2bfloat16(v.w);
    __nv_bfloat16 l0 = __float2bfloat16(v.x - __bfloat162float(h0));
    __nv_bfloat16 l1 = __float2bfloat16(v.y - __bfloat162float(h1));
    __nv_bfloat16 l2 = __float2bfloat16(v.z - __bfloat162float(h2));
    __nv_bfloat16 l3 = __float2bfloat16(v.w - __bfloat162float(h3));
    ((__nv_bfloat162*)hi)[i2]     = __halves2bfloat162(h0, h1);
    ((__nv_bfloat162*)hi)[i2 + 1] = __halves2bfloat162(h2, h3);
    ((__nv_bfloat162*)lo)[i2]     = __halves2bfloat162(l0, l1);
    ((__nv_bfloat162*)lo)[i2 + 1] = __halves2bfloat162(l2, l3);
}

__global__ void __launch_bounds__(256)
splitxy_kernel(const float* __restrict__ x, const float* __restrict__ y,
               __nv_bfloat16* __restrict__ xh, __nv_bfloat16* __restrict__ xl,
               __nv_bfloat16* __restrict__ yh, __nv_bfloat16* __restrict__ yl)
{
    int i = blockIdx.x * 256 + threadIdx.x;
    if (i < 1048576) split4(((const float4*)x)[i], xh, xl, 2 * (size_t)i);
    else {
        int j = i - 1048576;
        split4(((const float4*)y)[j], yh, yl, 2 * (size_t)j);
    }
}

__global__ void __launch_bounds__(256)
split6_kernel(const float* s0, const float* s1, const float* s2,
              const float* s3, const float* s4, const float* s5,
              const float* b0, const float* b1, const float* b2,
              const float* b3, const float* b4, const float* b5,
              __nv_bfloat16* __restrict__ hi, __nv_bfloat16* __restrict__ lo,
              float* __restrict__ biasC)
{
    if (blockIdx.x >= 6144) {
        int i = (blockIdx.x - 6144) * 256 + threadIdx.x;
        int slot = i >> 10, j = i & 1023;
        const float* src = (slot == 0) ? b0 : (slot == 1) ? b1 : (slot == 2) ? b2
                         : (slot == 3) ? b3 : (slot == 4) ? b4 : b5;
        biasC[i] = src[j];
        return;
    }
    int i = blockIdx.x * 256 + threadIdx.x;
    int slot = i >> 18, j = i & 262143;
    const float* src = (slot == 0) ? s0 : (slot == 1) ? s1 : (slot == 2) ? s2
                     : (slot == 3) ? s3 : (slot == 4) ? s4 : s5;
    split4(((const float4*)src)[j], hi, lo, 2 * (size_t)i);
}

// ============================================================================
// 128(M) x 256(N) x K=1024 hi/lo mainloop
// NOW 512 threads / 16 warps (4m x 4n), warp tile 32x64 — 4 warps per SMSP
// ============================================================================
#define PITCH    40
#define AREG_B   (128 * PITCH * 2)           // 10240
#define BREG_B   (256 * PITCH * 2)           // 20480
#define STAGE_B  (2 * AREG_B + 2 * BREG_B)   // 61440
#define GEMM_SMEM (3 * STAGE_B)              // 184320

__device__ __forceinline__ void load_stage(
    uint32_t sbase,
    const __nv_bfloat16* __restrict__ Ah, const __nv_bfloat16* __restrict__ Al,
    const __nv_bfloat16* __restrict__ Bh, const __nv_bfloat16* __restrict__ Bl,
    int mBase, int nBase, int k0, int tid)
{
    // 3072 16B-chunks: 0..511 Ahi, 512..1023 Alo, 1024..2047 Bhi, 2048..3071 Blo
#pragma unroll
    for (int j = 0; j < 6; ++j) {
        const int idx = j * 512 + tid;
        const int c = idx & 3;
        if (idx < 1024) {
            const int r = (idx & 511) >> 2;
            const __nv_bfloat16* src = (idx < 512) ? Ah : Al;
            const uint32_t dst = sbase + ((idx < 512) ? 0 : AREG_B);
            cp16(dst + r * (PITCH * 2) + c * 16,
                 src + (size_t)(mBase + r) * 1024 + k0 + c * 8);
        } else {
            const int q = idx - 1024;
            const int r = (q & 1023) >> 2;
            const __nv_bfloat16* src = (q < 1024) ? Bh : Bl;
            const uint32_t dst = sbase + 2 * AREG_B + ((q < 1024) ? 0 : BREG_B);
            cp16(dst + r * (PITCH * 2) + c * 16,
                 src + (size_t)(nBase + r) * 1024 + k0 + c * 8);
        }
    }
}

__device__ __forceinline__ void mainloop256(
    uint32_t sb,
    const __nv_bfloat16* __restrict__ Ah, const __nv_bfloat16* __restrict__ Al,
    const __nv_bfloat16* __restrict__ Bh, const __nv_bfloat16* __restrict__ Bl,
    int mBase, int nBase, int tid, int wid, int lid, float acc[2][8][4])
{
    const int wm = (wid >> 2) * 32;          // 4 m-groups of 32
    const int wn = (wid & 3) * 64;           // 4 n-groups of 64
    const int aRow = lid & 15, aCol = (lid >> 4) * 8;
    const int bRow = ((lid >> 4) & 1) * 8 + (lid & 7);
    const int bCol = ((lid >> 3) & 1) * 8;

    load_stage(sb, Ah, Al, Bh, Bl, mBase, nBase, 0, tid);
    asm volatile("cp.async.commit_group;" ::: "memory");
    load_stage(sb + STAGE_B, Ah, Al, Bh, Bl, mBase, nBase, 32, tid);
    asm volatile("cp.async.commit_group;" ::: "memory");

    for (int i = 0; i < 32; ++i) {
        if (i + 1 < 32) asm volatile("cp.async.wait_group 1;" ::: "memory");
        else            asm volatile("cp.async.wait_group 0;" ::: "memory");
        __syncthreads();
        if (i + 2 < 32) {
            load_stage(sb + ((i + 2) % 3) * STAGE_B, Ah, Al, Bh, Bl,
                       mBase, nBase, (i + 2) * 32, tid);
            asm volatile("cp.async.commit_group;" ::: "memory");
        }

        const uint32_t st = sb + (i % 3) * STAGE_B;
        const uint32_t sAh = st, sAl = st + AREG_B;
        const uint32_t sBh = st + 2 * AREG_B, sBl = sBh + BREG_B;

#pragma unroll
        for (int kk = 0; kk < 32; kk += 16) {
            uint32_t ah[2][4], al[2][4];
#pragma unroll
            for (int mt = 0; mt < 2; mt++) {
                const uint32_t ao = (wm + mt * 16 + aRow) * (PITCH * 2) + (kk + aCol) * 2;
                ldsm_x4(ah[mt][0], ah[mt][1], ah[mt][2], ah[mt][3], sAh + ao);
                ldsm_x4(al[mt][0], al[mt][1], al[mt][2], al[mt][3], sAl + ao);
            }
#pragma unroll
            for (int ntp = 0; ntp < 4; ntp++) {
                const uint32_t bo = (wn + ntp * 16 + bRow) * (PITCH * 2) + (kk + bCol) * 2;
                uint32_t bh4[4], bl4[4];
                ldsm_x4(bh4[0], bh4[1], bh4[2], bh4[3], sBh + bo);
                ldsm_x4(bl4[0], bl4[1], bl4[2], bl4[3], sBl + bo);
#pragma unroll
                for (int mt = 0; mt < 2; mt++) {
                    mma_bf16(acc[mt][2 * ntp],     ah[mt], &bh4[0]);
                    mma_bf16(acc[mt][2 * ntp],     al[mt], &bh4[0]);
                    mma_bf16(acc[mt][2 * ntp],     ah[mt], &bl4[0]);
                    mma_bf16(acc[mt][2 * ntp + 1], ah[mt], &bh4[2]);
                    mma_bf16(acc[mt][2 * ntp + 1], al[mt], &bh4[2]);
                    mma_bf16(acc[mt][2 * ntp + 1], ah[mt], &bl4[2]);
                }
            }
        }
    }
}

// ============================================================================
// fused projection GEMM (x -> QKV: grid 12x32; y -> KyVy: grid 8x32), 512 thr
// ============================================================================
__global__ void __launch_bounds__(512, 1)
proj_tc(const __nv_bfloat16* __restrict__ Ah, const __nv_bfloat16* __restrict__ Al,
        const __nv_bfloat16* __restrict__ Wh, const __nv_bfloat16* __restrict__ Wl,
        const float* __restrict__ biasC,
        __nv_bfloat16* __restrict__ Qh, __nv_bfloat16* __restrict__ Ql,
        __nv_bfloat16* __restrict__ Kh, __nv_bfloat16* __restrict__ Kl,
        __nv_bfloat16* __restrict__ Vh, __nv_bfloat16* __restrict__ Vl,
        int is_y)
{
    extern __shared__ __align__(128) char smem[];
    const uint32_t sb = (uint32_t)__cvta_generic_to_shared(smem);
    const int tid = threadIdx.x, wid = tid >> 5, lid = tid & 31;
    const int mBase = blockIdx.y * 128;
    const int nBase = blockIdx.x * 256;

    float acc[2][8][4];
#pragma unroll
    for (int mt = 0; mt < 2; mt++)
#pragma unroll
        for (int nt = 0; nt < 8; nt++)
#pragma unroll
            for (int e = 0; e < 4; e++) acc[mt][nt][e] = 0.f;

    mainloop256(sb, Ah, Al, Wh, Wl, mBase, nBase, tid, wid, lid, acc);

    const int wm = (wid >> 2) * 32, wn = (wid & 3) * 64;
    const int lr = lid >> 2, lc = (lid & 3) * 2;
    const int type0 = ((nBase + wn) >> 10) + is_y;      // 0=Q 1=K 2=V
    const float scale = (type0 == 0) ? 0.125f : 1.f;
    __nv_bfloat16 *oH, *oL;
    int Sst, mode;
    if (type0 == 0)      { oH = Qh; oL = Ql; Sst = SXX; mode = 1; }
    else if (type0 == 1) { oH = Kh; oL = Kl; Sst = SKK; mode = 1; }
    else                 { oH = Vh; oL = Vl; Sst = SKK; mode = 2; }
    const int seq_off = is_y ? SXX : 0;

#pragma unroll
    for (int mt = 0; mt < 2; mt++) {
#pragma unroll
        for (int half = 0; half < 2; half++) {
            const int m  = mBase + wm + mt * 16 + half * 8 + lr;
            const int bb = m >> 10, sdx = m & 1023;
#pragma unroll
            for (int nt = 0; nt < 8; nt++) {
                const int n = nBase + wn + nt * 8 + lc;
                const float v0 = (acc[mt][nt][half * 2 + 0] + biasC[n])     * scale;
                const float v1 = (acc[mt][nt][half * 2 + 1] + biasC[n + 1]) * scale;
                const __nv_bfloat16 h0 = __float2bfloat16(v0);
                const __nv_bfloat16 l0 = __float2bfloat16(v0 - __bfloat162float(h0));
                const __nv_bfloat16 h1 = __float2bfloat16(v1);
                const __nv_bfloat16 l1 = __float2bfloat16(v1 - __bfloat162float(h1));
                const int ncol = n & 1023;
                const int hh = ncol >> 6, d = ncol & 63;
                if (mode == 1) {
                    size_t idx = (((size_t)(bb * NH + hh)) * Sst + seq_off + sdx) * DH + d;
                    *(__nv_bfloat162*)&oH[idx] = __halves2bfloat162(h0, h1);
                    *(__nv_bfloat162*)&oL[idx] = __halves2bfloat162(l0, l1);
                } else {
                    size_t idx = (((size_t)(bb * NH + hh)) * DH + d) * (size_t)Sst
                               + seq_off + sdx;
                    oH[idx] = h0; oL[idx] = l0;
                    oH[idx + Sst] = h1; oL[idx + Sst] = l1;
                }
            }
        }
    }
}

// out projection (grid 4x32, 512 thr): fp32 flat [m, 1024]
__global__ void __launch_bounds__(512, 1)
gemm_out(const __nv_bfloat16* __restrict__ Ah, const __nv_bfloat16* __restrict__ Al,
         const __nv_bfloat16* __restrict__ Wh, const __nv_bfloat16* __restrict__ Wl,
         const float* __restrict__ bias, float* __restrict__ outF)
{
    extern __shared__ __align__(128) char smem[];
    const uint32_t sb = (uint32_t)__cvta_generic_to_shared(smem);
    const int tid = threadIdx.x, wid = tid >> 5, lid = tid & 31;
    const int mBase = blockIdx.y * 128;
    const int nBase = blockIdx.x * 256;

    float acc[2][8][4];
#pragma unroll
    for (int mt = 0; mt < 2; mt++)
#pragma unroll
        for (int nt = 0; nt < 8; nt++)
#pragma unroll
            for (int e = 0; e < 4; e++) acc[mt][nt][e] = 0.f;

    mainloop256(sb, Ah, Al, Wh, Wl, mBase, nBase, tid, wid, lid, acc);

    const int wm = (wid >> 2) * 32, wn = (wid & 3) * 64;
    const int lr = lid >> 2, lc = (lid & 3) * 2;
#pragma unroll
    for (int mt = 0; mt < 2; mt++)
#pragma unroll
        for (int half = 0; half < 2; half++) {
            const int m = mBase + wm + mt * 16 + half * 8 + lr;
#pragma unroll
            for (int nt = 0; nt < 8; nt++) {
                const int n = nBase + wn + nt * 8 + lc;
                *(float2*)&outF[(size_t)m * DIMN + n] = make_float2(
                    acc[mt][nt][half * 2 + 0] + bias[n],
                    acc[mt][nt][half * 2 + 1] + bias[n + 1]);
            }
        }
}

// ============================================================================
// tensor-core flash attention (unchanged from R7)
// ============================================================================
#define APITCH   72
#define ATILE_B  (64 * APITCH * 2)           // 9216
#define ASTAGE_B (4 * ATILE_B)               // 36864
#define ATTN_SMEM (3 * ASTAGE_B)             // 110592

__device__ __forceinline__ void load_kv(
    uint32_t dst,
    const __nv_bfloat16* __restrict__ Kh_g, const __nv_bfloat16* __restrict__ Kl_g,
    const __nv_bfloat16* __restrict__ Vh_g, const __nv_bfloat16* __restrict__ Vl_g,
    int kt, int tid)
{
#pragma unroll
    for (int j = 0; j < 8; ++j) {
        const int t = j >> 1;
        const int q = (j & 1) * 256 + tid;
        const int r = q >> 3, c = q & 7;
        const uint32_t da = dst + t * ATILE_B + r * (APITCH * 2) + c * 16;
        if (t == 0)      cp16(da, Kh_g + (size_t)(kt * 64 + r) * 64 + c * 8);
        else if (t == 1) cp16(da, Kl_g + (size_t)(kt * 64 + r) * 64 + c * 8);
        else if (t == 2) cp16(da, Vh_g + (size_t)r * SKK + kt * 64 + c * 8);
        else             cp16(da, Vl_g + (size_t)r * SKK + kt * 64 + c * 8);
    }
}

__global__ void __launch_bounds__(256, 1)
attn_tc(const __nv_bfloat16* __restrict__ Qh, const __nv_bfloat16* __restrict__ Ql,
        const __nv_bfloat16* __restrict__ Kh, const __nv_bfloat16* __restrict__ Kl,
        const __nv_bfloat16* __restrict__ Vth, const __nv_bfloat16* __restrict__ Vtl,
        __nv_bfloat16* __restrict__ Oh, __nv_bfloat16* __restrict__ Ol)
{
    extern __shared__ __align__(128) char smem[];
    const uint32_t sb = (uint32_t)__cvta_generic_to_shared(smem);
    const int tid = threadIdx.x, wid = tid >> 5, lid = tid & 31;
    const int qt = blockIdx.x, h = blockIdx.y, b = blockIdx.z;

    const __nv_bfloat16* Qgh = Qh + ((size_t)(b * NH + h) * SXX + qt * 128) * DH;
    const __nv_bfloat16* Qgl = Ql + ((size_t)(b * NH + h) * SXX + qt * 128) * DH;
    const __nv_bfloat16* Kgh = Kh + (size_t)(b * NH + h) * SKK * DH;
    const __nv_bfloat16* Kgl = Kl + (size_t)(b * NH + h) * SKK * DH;
    const __nv_bfloat16* Vgh = Vth + (size_t)(b * NH + h) * DH * SKK;
    const __nv_bfloat16* Vgl = Vtl + (size_t)(b * NH + h) * DH * SKK;

    load_kv(sb, Kgh, Kgl, Vgh, Vgl, 0, tid);
    asm volatile("cp.async.commit_group;" ::: "memory");
    load_kv(sb + ASTAGE_B, Kgh, Kgl, Vgh, Vgl, 1, tid);
    asm volatile("cp.async.commit_group;" ::: "memory");
#pragma unroll
    for (int j = 0; j < 4; ++j) {
        const int q = j * 256 + tid;
        const int r = q >> 3, c = q & 7;
        cp16(sb + 2 * ASTAGE_B + r * (APITCH * 2) + c * 16, Qgh + (size_t)r * 64 + c * 8);
        cp16(sb + 2 * ASTAGE_B + 18432 + r * (APITCH * 2) + c * 16,
             Qgl + (size_t)r * 64 + c * 8);
    }
    asm volatile("cp.async.commit_group;" ::: "memory");
    asm volatile("cp.async.wait_group 0;" ::: "memory");
    __syncthreads();

    uint32_t qhf[4][4], qlf[4][4];
    const int aRow = lid & 15, aCol = (lid >> 4) * 8;
#pragma unroll
    for (int kd = 0; kd < 4; kd++) {
        const uint32_t ao = (wid * 16 + aRow) * (APITCH * 2) + (kd * 16 + aCol) * 2;
        ldsm_x4(qhf[kd][0], qhf[kd][1], qhf[kd][2], qhf[kd][3], sb + 2 * ASTAGE_B + ao);
        ldsm_x4(qlf[kd][0], qlf[kd][1], qlf[kd][2], qlf[kd][3],
                sb + 2 * ASTAGE_B + 18432 + ao);
    }

    float m0 = -1e30f, m1 = -1e30f, l0 = 0.f, l1 = 0.f;
    float oacc[8][4];
#pragma unroll
    for (int dt = 0; dt < 8; dt++)
#pragma unroll
        for (int e = 0; e < 4; e++) oacc[dt][e] = 0.f;

    const int bRow = ((lid >> 4) & 1) * 8 + (lid & 7);
    const int bCol = ((lid >> 3) & 1) * 8;

#pragma unroll 1
    for (int kt = 0; kt < 32; ++kt) {
        if (kt + 1 < 32) asm volatile("cp.async.wait_group 1;" ::: "memory");
        else             asm volatile("cp.async.wait_group 0;" ::: "memory");
        __syncthreads();
        if (kt + 2 < 32) {
            load_kv(sb + ((kt + 2) % 3) * ASTAGE_B, Kgh, Kgl, Vgh, Vgl, kt + 2, tid);
            asm volatile("cp.async.commit_group;" ::: "memory");
        }
        const uint32_t st = sb + (kt % 3) * ASTAGE_B;

        float sc[8][4];
#pragma unroll
        for (int nt = 0; nt < 8; nt++)
#pragma unroll
            for (int e = 0; e < 4; e++) sc[nt][e] = 0.f;
#pragma unroll
        for (int kd = 0; kd < 4; kd++) {
#pragma unroll
            for (int ntp = 0; ntp < 4; ntp++) {
                const uint32_t bo = (ntp * 16 + bRow) * (APITCH * 2) + (kd * 16 + bCol) * 2;
                uint32_t kh4[4], kl4[4];
                ldsm_x4(kh4[0], kh4[1], kh4[2], kh4[3], st + bo);
                ldsm_x4(kl4[0], kl4[1], kl4[2], kl4[3], st + ATILE_B + bo);
                mma_bf16(sc[2 * ntp],     qhf[kd], &kh4[0]);
                mma_bf16(sc[2 * ntp],     qlf[kd], &kh4[0]);
                mma_bf16(sc[2 * ntp],     qhf[kd], &kl4[0]);
                mma_bf16(sc[2 * ntp + 1], qhf[kd], &kh4[2]);
                mma_bf16(sc[2 * ntp + 1], qlf[kd], &kh4[2]);
                mma_bf16(sc[2 * ntp + 1], qhf[kd], &kl4[2]);
            }
        }

        float mx0 = -1e30f, mx1 = -1e30f;
#pragma unroll
        for (int nt = 0; nt < 8; nt++) {
            mx0 = fmaxf(mx0, fmaxf(sc[nt][0], sc[nt][1]));
            mx1 = fmaxf(mx1, fmaxf(sc[nt][2], sc[nt][3]));
        }
        mx0 = fmaxf(mx0, __shfl_xor_sync(0xffffffffu, mx0, 1));
        mx0 = fmaxf(mx0, __shfl_xor_sync(0xffffffffu, mx0, 2));
        mx1 = fmaxf(mx1, __shfl_xor_sync(0xffffffffu, mx1, 1));
        mx1 = fmaxf(mx1, __shfl_xor_sync(0xffffffffu, mx1, 2));
        const float mn0 = fmaxf(m0, mx0), mn1 = fmaxf(m1, mx1);
        const float al0 = __expf(m0 - mn0), al1 = __expf(m1 - mn1);
        m0 = mn0; m1 = mn1;
        float rs0 = 0.f, rs1 = 0.f;
#pragma unroll
        for (int nt = 0; nt < 8; nt++) {
            sc[nt][0] = __expf(sc[nt][0] - m0);
            sc[nt][1] = __expf(sc[nt][1] - m0);
            sc[nt][2] = __expf(sc[nt][2] - m1);
            sc[nt][3] = __expf(sc[nt][3] - m1);
            rs0 += sc[nt][0] + sc[nt][1];
            rs1 += sc[nt][2] + sc[nt][3];
        }
        rs0 += __shfl_xor_sync(0xffffffffu, rs0, 1);
        rs0 += __shfl_xor_sync(0xffffffffu, rs0, 2);
        rs1 += __shfl_xor_sync(0xffffffffu, rs1, 1);
        rs1 += __shfl_xor_sync(0xffffffffu, rs1, 2);
        l0 = l0 * al0 + rs0;
        l1 = l1 * al1 + rs1;
#pragma unroll
        for (int dt = 0; dt < 8; dt++) {
            oacc[dt][0] *= al0; oacc[dt][1] *= al0;
            oacc[dt][2] *= al1; oacc[dt][3] *= al1;
        }

#pragma unroll
        for (int ks = 0; ks < 4; ks++) {
            float p0 = sc[2 * ks][0],     p1 = sc[2 * ks][1];
            float p2 = sc[2 * ks][2],     p3 = sc[2 * ks][3];
            float p4 = sc[2 * ks + 1][0], p5 = sc[2 * ks + 1][1];
            float p6 = sc[2 * ks + 1][2], p7 = sc[2 * ks + 1][3];
            uint32_t pha[4], pla[4];
            pha[0] = pack_bf16(p0, p1); pha[1] = pack_bf16(p2, p3);
            pha[2] = pack_bf16(p4, p5); pha[3] = pack_bf16(p6, p7);
            pla[0] = pack_bf16(p0 - __bfloat162float(__float2bfloat16(p0)),
                               p1 - __bfloat162float(__float2bfloat16(p1)));
            pla[1] = pack_bf16(p2 - __bfloat162float(__float2bfloat16(p2)),
                               p3 - __bfloat162float(__float2bfloat16(p3)));
            pla[2] = pack_bf16(p4 - __bfloat162float(__float2bfloat16(p4)),
                               p5 - __bfloat162float(__float2bfloat16(p5)));
            pla[3] = pack_bf16(p6 - __bfloat162float(__float2bfloat16(p6)),
                               p7 - __bfloat162float(__float2bfloat16(p7)));
#pragma unroll
            for (int dtp = 0; dtp < 4; dtp++) {
                const uint32_t vo = (dtp * 16 + bRow) * (APITCH * 2) + (ks * 16 + bCol) * 2;
                uint32_t vh4[4], vl4[4];
                ldsm_x4(vh4[0], vh4[1], vh4[2], vh4[3], st + 2 * ATILE_B + vo);
                ldsm_x4(vl4[0], vl4[1], vl4[2], vl4[3], st + 3 * ATILE_B + vo);
                mma_bf16(oacc[2 * dtp],     pha, &vh4[0]);
                mma_bf16(oacc[2 * dtp],     pla, &vh4[0]);
                mma_bf16(oacc[2 * dtp],     pha, &vl4[0]);
                mma_bf16(oacc[2 * dtp + 1], pha, &vh4[2]);
                mma_bf16(oacc[2 * dtp + 1], pla, &vh4[2]);
                mma_bf16(oacc[2 * dtp + 1], pha, &vl4[2]);
            }
        }
    }

    const float inv0 = 1.f / l0, inv1 = 1.f / l1;
    const int row0 = qt * 128 + wid * 16 + (lid >> 2);
    const int row1 = row0 + 8;
    const int lc = (lid & 3) * 2;
#pragma unroll
    for (int dt = 0; dt < 8; dt++) {
        const int col = h * 64 + dt * 8 + lc;
        {
            const float v0 = oacc[dt][0] * inv0, v1 = oacc[dt][1] * inv0;
            const __nv_bfloat16 h0 = __float2bfloat16(v0);
            const __nv_bfloat16 e0 = __float2bfloat16(v0 - __bfloat162float(h0));
            const __nv_bfloat16 h1 = __float2bfloat16(v1);
            const __nv_bfloat16 e1 = __float2bfloat16(v1 - __bfloat162float(h1));
            const size_t i0 = ((size_t)b * SXX + row0) * DIMN + col;
            *(__nv_bfloat162*)&Oh[i0] = __halves2bfloat162(h0, h1);
            *(__nv_bfloat162*)&Ol[i0] = __halves2bfloat162(e0, e1);
        }
        {
            const float v0 = oacc[dt][2] * inv1, v1 = oacc[dt][3] * inv1;
            const __nv_bfloat16 h0 = __float2bfloat16(v0);
            const __nv_bfloat16 e0 = __float2bfloat16(v0 - __bfloat162float(h0));
            const __nv_bfloat16 h1 = __float2bfloat16(v1);
            const __nv_bfloat16 e1 = __float2bfloat16(v1 - __bfloat162float(h1));
            const size_t i1 = ((size_t)b * SXX + row1) * DIMN + col;
            *(__nv_bfloat162*)&Oh[i1] = __halves2bfloat162(h0, h1);
            *(__nv_bfloat162*)&Ol[i1] = __halves2bfloat162(e0, e1);
        }
    }
}

// ============================================================================
// launch
// ============================================================================
extern "C" void kernel_launch(void* const* d_in, const int* in_sizes, int n_in,
                              void* d_out, int out_size)
{
    const float* x     = (const float*)d_in[0];
    const float* y     = (const float*)d_in[1];
    const float* W_Kx  = (const float*)d_in[2];
    const float* b_Kx  = (const float*)d_in[3];
    const float* W_Qx  = (const float*)d_in[4];
    const float* b_Qx  = (const float*)d_in[5];
    const float* W_Vx  = (const float*)d_in[6];
    const float* b_Vx  = (const float*)d_in[7];
    const float* W_Ky  = (const float*)d_in[8];
    const float* b_Ky  = (const float*)d_in[9];
    const float* W_Vy  = (const float*)d_in[10];
    const float* b_Vy  = (const float*)d_in[11];
    const float* W_out = (const float*)d_in[12];
    const float* b_out = (const float*)d_in[13];
    float* out = (float*)d_out;

    __nv_bfloat16 *xh, *xl, *yh, *yl, *Wh, *Wl;
    __nv_bfloat16 *Qhp, *Qlp, *Khp, *Klp, *Vhp, *Vlp, *Ohp, *Olp;
    float* biasC;
    cudaGetSymbolAddress((void**)&xh, g_xh);   cudaGetSymbolAddress((void**)&xl, g_xl);
    cudaGetSymbolAddress((void**)&yh, g_yh);   cudaGetSymbolAddress((void**)&yl, g_yl);
    cudaGetSymbolAddress((void**)&Wh, g_Wh);   cudaGetSymbolAddress((void**)&Wl, g_Wl);
    cudaGetSymbolAddress((void**)&biasC, g_bias);
    cudaGetSymbolAddress((void**)&Qhp, g_Qh);  cudaGetSymbolAddress((void**)&Qlp, g_Ql);
    cudaGetSymbolAddress((void**)&Khp, g_Kh);  cudaGetSymbolAddress((void**)&Klp, g_Kl);
    cudaGetSymbolAddress((void**)&Vhp, g_Vth); cudaGetSymbolAddress((void**)&Vlp, g_Vtl);
    cudaGetSymbolAddress((void**)&Ohp, g_Oh);  cudaGetSymbolAddress((void**)&Olp, g_Ol);

    splitxy_kernel<<<8192, 256>>>(x, y, xh, xl, yh, yl);
    split6_kernel<<<6168, 256>>>(W_Qx, W_Kx, W_Vx, W_Ky, W_Vy, W_out,
                                 b_Qx, b_Kx, b_Vx, b_Ky, b_Vy, b_out,
                                 Wh, Wl, biasC);

    cudaFuncSetAttribute(proj_tc,  cudaFuncAttributeMaxDynamicSharedMemorySize, GEMM_SMEM);
    cudaFuncSetAttribute(gemm_out, cudaFuncAttributeMaxDynamicSharedMemorySize, GEMM_SMEM);
    cudaFuncSetAttribute(attn_tc,  cudaFuncAttributeMaxDynamicSharedMemorySize, ATTN_SMEM);

    proj_tc<<<dim3(12, 32), 512, GEMM_SMEM>>>(xh, xl, Wh, Wl, biasC,
                                              Qhp, Qlp, Khp, Klp, Vhp, Vlp, 0);
    proj_tc<<<dim3(8, 32), 512, GEMM_SMEM>>>(yh, yl, Wh + 3 * 1048576ull,
                                             Wl + 3 * 1048576ull, biasC + 3 * 1024,
                                             Qhp, Qlp, Khp, Klp, Vhp, Vlp, 1);

    attn_tc<<<dim3(8, 16, 4), 256, ATTN_SMEM>>>(Qhp, Qlp, Khp, Klp, Vhp, Vlp, Ohp, Olp);

    gemm_out<<<dim3(4, 32), 512, GEMM_SMEM>>>(Ohp, Olp, Wh + 5 * 1048576ull,
                                              Wl + 5 * 1048576ull, b_out, out);
}